// round 1
// baseline (speedup 1.0000x reference)
#include <cuda_runtime.h>
#include <cuda_bf16.h>
#include <math.h>

// Problem constants
#define BB 2
#define SS 2048
#define HID 2048
#define NH 16
#define NKVH 2
#define DH 256
#define ROT 64
#define MM (BB*SS)          // 4096 tokens
#define QGN (NH*DH*2)       // 8192
#define KVN (NKVH*DH)       // 512
#define ODIM (NH*DH)        // 4096

// Scratch (device globals; allocation-free per harness rules)
__device__ float g_qg[(size_t)MM * QGN];     // [token][h*512 + (0..255 q | 256..511 gate)]
__device__ float g_k [(size_t)MM * KVN];
__device__ float g_v [(size_t)MM * KVN];
__device__ float g_q [(size_t)BB * NH  * SS * DH];   // [b][h][s][d]
__device__ float g_kr[(size_t)BB * NKVH * SS * DH];
__device__ float g_vr[(size_t)BB * NKVH * SS * DH];
__device__ float g_attn[(size_t)MM * ODIM];          // [token][h*256+d]

// ---------------------------------------------------------------------------
// Generic fp32 SGEMM: C[M,N] = A[M,K] @ B[K,N], all row-major.
// 128x128 block tile, K-step 8, 256 threads, 8x8 per-thread microtile.
// M,N multiples of 128; K multiple of 8 (true for all our shapes).
// ---------------------------------------------------------------------------
__global__ __launch_bounds__(256) void sgemm_kernel(
    const float* __restrict__ A, const float* __restrict__ B,
    float* __restrict__ C, int M, int N, int K)
{
    __shared__ float As[8][132];   // [k][row], padded
    __shared__ float Bs[8][128];   // [k][col]

    const int tid = threadIdx.x;
    const int bx = blockIdx.x, by = blockIdx.y;
    const int tx = tid & 15, ty = tid >> 4;

    const int arow = tid >> 1;            // 0..127
    const int acol = (tid & 1) * 4;       // 0 or 4
    const int brow = tid >> 5;            // 0..7
    const int bcol = (tid & 31) * 4;      // 0..124

    const float* Ab = A + (size_t)(by * 128 + arow) * K + acol;
    const float* Bb = B + (size_t)brow * N + bx * 128 + bcol;

    float acc[8][8];
#pragma unroll
    for (int i = 0; i < 8; i++)
#pragma unroll
        for (int j = 0; j < 8; j++) acc[i][j] = 0.f;

    for (int k0 = 0; k0 < K; k0 += 8) {
        float4 av = *(const float4*)(Ab + k0);
        float4 bv = *(const float4*)(Bb + (size_t)k0 * N);
        __syncthreads();
        As[acol + 0][arow] = av.x;
        As[acol + 1][arow] = av.y;
        As[acol + 2][arow] = av.z;
        As[acol + 3][arow] = av.w;
        *(float4*)&Bs[brow][bcol] = bv;
        __syncthreads();
#pragma unroll
        for (int kk = 0; kk < 8; kk++) {
            float a[8], b[8];
            *(float4*)(a)     = *(const float4*)&As[kk][ty * 4];
            *(float4*)(a + 4) = *(const float4*)&As[kk][64 + ty * 4];
            *(float4*)(b)     = *(const float4*)&Bs[kk][tx * 4];
            *(float4*)(b + 4) = *(const float4*)&Bs[kk][64 + tx * 4];
#pragma unroll
            for (int i = 0; i < 8; i++)
#pragma unroll
                for (int j = 0; j < 8; j++)
                    acc[i][j] += a[i] * b[j];
        }
    }

    const int cb = bx * 128;
#pragma unroll
    for (int i = 0; i < 8; i++) {
        int r = by * 128 + ((i < 4) ? (ty * 4 + i) : (64 + ty * 4 + (i - 4)));
        float4 v0 = make_float4(acc[i][0], acc[i][1], acc[i][2], acc[i][3]);
        float4 v1 = make_float4(acc[i][4], acc[i][5], acc[i][6], acc[i][7]);
        *(float4*)(C + (size_t)r * N + cb + tx * 4)      = v0;
        *(float4*)(C + (size_t)r * N + cb + 64 + tx * 4) = v1;
    }
}

// ---------------------------------------------------------------------------
// Post-process: RMSNorm + RoPE for Q (16 heads) and K (2 heads), reshape V.
// grid: (4096 tokens, 20 units). block: 256 threads (one per dim).
// ---------------------------------------------------------------------------
__global__ __launch_bounds__(256) void qkv_post_kernel(
    const float* __restrict__ cosp, const float* __restrict__ sinp,
    const float* __restrict__ qw, const float* __restrict__ kw)
{
    const int token = blockIdx.x;
    const int unit  = blockIdx.y;
    const int d     = threadIdx.x;
    const int b = token >> 11;      // S = 2048
    const int s = token & 2047;

    __shared__ float sh[DH];
    __shared__ float red[8];

    if (unit < 18) {
        float x;
        const float* w;
        if (unit < 16) {
            x = g_qg[(size_t)token * QGN + unit * 512 + d];
            w = qw;
        } else {
            x = g_k[(size_t)token * KVN + (unit - 16) * 256 + d];
            w = kw;
        }
        float v = x * x;
#pragma unroll
        for (int o = 16; o; o >>= 1) v += __shfl_xor_sync(0xffffffffu, v, o);
        if ((d & 31) == 0) red[d >> 5] = v;
        __syncthreads();
        float tot = 0.f;
#pragma unroll
        for (int i = 0; i < 8; i++) tot += red[i];
        float xn = x * rsqrtf(tot * (1.0f / 256.0f) + 1e-6f) * (1.0f + w[d]);
        sh[d] = xn;
        __syncthreads();
        float out = xn;
        if (d < ROT) {
            float rot = (d < 32) ? -sh[d + 32] : sh[d - 32];
            out = xn * cosp[(size_t)token * ROT + d] + rot * sinp[(size_t)token * ROT + d];
        }
        if (unit < 16)
            g_q[(((size_t)b * NH + unit) * SS + s) * DH + d] = out;
        else
            g_kr[(((size_t)b * NKVH + (unit - 16)) * SS + s) * DH + d] = out;
    } else {
        const int kvh = unit - 18;
        g_vr[(((size_t)b * NKVH + kvh) * SS + s) * DH + d] =
            g_v[(size_t)token * KVN + kvh * 256 + d];
    }
}

// ---------------------------------------------------------------------------
// Flash attention (causal, GQA rep=8), fused gate-sigmoid epilogue.
// 64x64 tiles, D chunked by 64 through SMEM. 256 threads, 4x4 micro-tile.
// grid: (32 q-tiles, B*H=32).
// ---------------------------------------------------------------------------
#define FA_SMEM_FLOATS (64*65*2 + 64*68*2)

__global__ __launch_bounds__(256) void flash_kernel()
{
    extern __shared__ float sm[];
    float* Qct = sm;                 // [d][row] stride 65
    float* Kct = Qct + 64 * 65;      // [d][key] stride 65
    float* Ps  = Kct + 64 * 65;      // [row][key] stride 68
    float* Vc  = Ps + 64 * 68;       // [key][d] stride 68

    const int tid = threadIdx.x;
    const int tx = tid & 15, ty = tid >> 4;
    const int qt = blockIdx.x;
    const int b  = blockIdx.y >> 4;
    const int h  = blockIdx.y & 15;
    const int kvh = h >> 3;
    const int q0 = qt * 64;

    const float* Qp = g_q  + (((size_t)b * NH + h) * SS + q0) * DH;
    const float* Kp = g_kr + (((size_t)b * NKVH + kvh) * SS) * DH;
    const float* Vp = g_vr + (((size_t)b * NKVH + kvh) * SS) * DH;

    float o[4][16];
    float m[4], l[4];
#pragma unroll
    for (int i = 0; i < 4; i++) {
        m[i] = -1e30f; l[i] = 0.f;
#pragma unroll
        for (int t = 0; t < 16; t++) o[i][t] = 0.f;
    }

    const int lr  = tid >> 4;          // loader row 0..15
    const int ld4 = (tid & 15) * 4;    // loader dim*4

    for (int kt = 0; kt <= qt; kt++) {
        float s[4][4];
#pragma unroll
        for (int i = 0; i < 4; i++)
#pragma unroll
            for (int j = 0; j < 4; j++) s[i][j] = 0.f;

        // ----- scores: S = Q K^T over D=256 in 4 chunks of 64 -----
        for (int c = 0; c < 4; c++) {
            __syncthreads();
#pragma unroll
            for (int it = 0; it < 4; it++) {
                int r = lr + it * 16;
                float4 qv = *(const float4*)(Qp + (size_t)r * DH + c * 64 + ld4);
                Qct[(ld4 + 0) * 65 + r] = qv.x;
                Qct[(ld4 + 1) * 65 + r] = qv.y;
                Qct[(ld4 + 2) * 65 + r] = qv.z;
                Qct[(ld4 + 3) * 65 + r] = qv.w;
                float4 kv = *(const float4*)(Kp + (size_t)(kt * 64 + r) * DH + c * 64 + ld4);
                Kct[(ld4 + 0) * 65 + r] = kv.x;
                Kct[(ld4 + 1) * 65 + r] = kv.y;
                Kct[(ld4 + 2) * 65 + r] = kv.z;
                Kct[(ld4 + 3) * 65 + r] = kv.w;
            }
            __syncthreads();
#pragma unroll 8
            for (int dd = 0; dd < 64; dd++) {
                float a0 = Qct[dd * 65 + ty * 4 + 0];
                float a1 = Qct[dd * 65 + ty * 4 + 1];
                float a2 = Qct[dd * 65 + ty * 4 + 2];
                float a3 = Qct[dd * 65 + ty * 4 + 3];
                float b0 = Kct[dd * 65 + tx * 4 + 0];
                float b1 = Kct[dd * 65 + tx * 4 + 1];
                float b2 = Kct[dd * 65 + tx * 4 + 2];
                float b3 = Kct[dd * 65 + tx * 4 + 3];
                s[0][0] += a0 * b0; s[0][1] += a0 * b1; s[0][2] += a0 * b2; s[0][3] += a0 * b3;
                s[1][0] += a1 * b0; s[1][1] += a1 * b1; s[1][2] += a1 * b2; s[1][3] += a1 * b3;
                s[2][0] += a2 * b0; s[2][1] += a2 * b1; s[2][2] += a2 * b2; s[2][3] += a2 * b3;
                s[3][0] += a3 * b0; s[3][1] += a3 * b1; s[3][2] += a3 * b2; s[3][3] += a3 * b3;
            }
        }

        // ----- scale + causal mask (diag tile only) -----
        const float SCALE = 0.0625f;  // 1/sqrt(256)
        if (kt == qt) {
#pragma unroll
            for (int i = 0; i < 4; i++)
#pragma unroll
                for (int j = 0; j < 4; j++)
                    s[i][j] = (tx * 4 + j > ty * 4 + i) ? -1e30f : s[i][j] * SCALE;
        } else {
#pragma unroll
            for (int i = 0; i < 4; i++)
#pragma unroll
                for (int j = 0; j < 4; j++) s[i][j] *= SCALE;
        }

        // ----- online softmax (rows span 16 tx lanes within each half-warp) --
#pragma unroll
        for (int i = 0; i < 4; i++) {
            float rm = fmaxf(fmaxf(s[i][0], s[i][1]), fmaxf(s[i][2], s[i][3]));
#pragma unroll
            for (int off = 8; off; off >>= 1)
                rm = fmaxf(rm, __shfl_xor_sync(0xffffffffu, rm, off));
            float mn = fmaxf(m[i], rm);
            float alpha = __expf(m[i] - mn);
            m[i] = mn;
            float rs = 0.f;
#pragma unroll
            for (int j = 0; j < 4; j++) { s[i][j] = __expf(s[i][j] - mn); rs += s[i][j]; }
#pragma unroll
            for (int off = 8; off; off >>= 1)
                rs += __shfl_xor_sync(0xffffffffu, rs, off);
            l[i] = l[i] * alpha + rs;
#pragma unroll
            for (int t = 0; t < 16; t++) o[i][t] *= alpha;
            *(float4*)&Ps[(ty * 4 + i) * 68 + tx * 4] =
                make_float4(s[i][0], s[i][1], s[i][2], s[i][3]);
        }

        // ----- O += P V  (V in 4 d-chunks of 64) -----
        for (int c = 0; c < 4; c++) {
            __syncthreads();
#pragma unroll
            for (int it = 0; it < 4; it++) {
                int r = lr + it * 16;
                *(float4*)&Vc[r * 68 + ld4] =
                    *(const float4*)(Vp + (size_t)(kt * 64 + r) * DH + c * 64 + ld4);
            }
            __syncthreads();
#pragma unroll 8
            for (int key = 0; key < 64; key++) {
                float4 v = *(const float4*)&Vc[key * 68 + tx * 4];
#pragma unroll
                for (int i = 0; i < 4; i++) {
                    float p = Ps[(ty * 4 + i) * 68 + key];
                    o[i][c * 4 + 0] += p * v.x;
                    o[i][c * 4 + 1] += p * v.y;
                    o[i][c * 4 + 2] += p * v.z;
                    o[i][c * 4 + 3] += p * v.w;
                }
            }
        }
    }

    // ----- epilogue: /l, * sigmoid(gate), write to attn matrix -----
#pragma unroll
    for (int i = 0; i < 4; i++) {
        int r = q0 + ty * 4 + i;
        size_t token = (size_t)b * SS + r;
        float inv = 1.f / l[i];
#pragma unroll
        for (int c = 0; c < 4; c++) {
            int d = c * 64 + tx * 4;
            float4 g = *(const float4*)(g_qg + token * QGN + h * 512 + 256 + d);
            float4 ov;
            ov.x = o[i][c * 4 + 0] * inv / (1.f + __expf(-g.x));
            ov.y = o[i][c * 4 + 1] * inv / (1.f + __expf(-g.y));
            ov.z = o[i][c * 4 + 2] * inv / (1.f + __expf(-g.z));
            ov.w = o[i][c * 4 + 3] * inv / (1.f + __expf(-g.w));
            *(float4*)(g_attn + token * ODIM + h * 256 + d) = ov;
        }
    }
}

// ---------------------------------------------------------------------------
extern "C" void kernel_launch(void* const* d_in, const int* in_sizes, int n_in,
                              void* d_out, int out_size)
{
    (void)in_sizes; (void)n_in; (void)out_size;
    const float* hs   = (const float*)d_in[0];
    const float* cosp = (const float*)d_in[1];
    const float* sinp = (const float*)d_in[2];
    const float* Wq   = (const float*)d_in[3];
    const float* Wk   = (const float*)d_in[4];
    const float* Wv   = (const float*)d_in[5];
    const float* Wo   = (const float*)d_in[6];
    const float* qw   = (const float*)d_in[7];
    const float* kw   = (const float*)d_in[8];
    float* out = (float*)d_out;

    float *p_qg, *p_k, *p_v, *p_attn;
    cudaGetSymbolAddress((void**)&p_qg,   g_qg);
    cudaGetSymbolAddress((void**)&p_k,    g_k);
    cudaGetSymbolAddress((void**)&p_v,    g_v);
    cudaGetSymbolAddress((void**)&p_attn, g_attn);

    // 1) Projections
    sgemm_kernel<<<dim3(QGN / 128, MM / 128), 256>>>(hs, Wq, p_qg, MM, QGN, HID);
    sgemm_kernel<<<dim3(KVN / 128, MM / 128), 256>>>(hs, Wk, p_k,  MM, KVN, HID);
    sgemm_kernel<<<dim3(KVN / 128, MM / 128), 256>>>(hs, Wv, p_v,  MM, KVN, HID);

    // 2) RMSNorm + RoPE + reshape
    qkv_post_kernel<<<dim3(MM, 20), 256>>>(cosp, sinp, qw, kw);

    // 3) Flash attention + gate
    static const int fa_smem = FA_SMEM_FLOATS * (int)sizeof(float);
    cudaFuncSetAttribute(flash_kernel, cudaFuncAttributeMaxDynamicSharedMemorySize, fa_smem);
    flash_kernel<<<dim3(SS / 64, BB * NH), 256, fa_smem>>>();

    // 4) Output projection
    sgemm_kernel<<<dim3(HID / 128, MM / 128), 256>>>(p_attn, Wo, out, MM, HID, ODIM);
}

// round 2
// speedup vs baseline: 1.5837x; 1.5837x over previous
#include <cuda_runtime.h>
#include <cuda_bf16.h>
#include <math.h>

// Problem constants
#define BB 2
#define SS 2048
#define HID 2048
#define NH 16
#define NKVH 2
#define DH 256
#define ROT 64
#define MM (BB*SS)          // 4096 tokens
#define QGN (NH*DH*2)       // 8192
#define KVN (NKVH*DH)       // 512
#define ODIM (NH*DH)        // 4096

// Scratch (device globals; allocation-free per harness rules)
__device__ float g_qg[(size_t)MM * QGN];     // [token][h*512 + (0..255 q | 256..511 gate)]
__device__ float g_k [(size_t)MM * KVN];
__device__ float g_v [(size_t)MM * KVN];
__device__ float g_q [(size_t)BB * NH  * SS * DH];   // [b][h][s][d]
__device__ float g_kr[(size_t)BB * NKVH * SS * DH];
__device__ float g_vr[(size_t)BB * NKVH * SS * DH];
__device__ float g_attn[(size_t)MM * ODIM];          // [token][h*256+d]

// ---------------------------------------------------------------------------
// tf32 tensor-core GEMM: C[M,N] = A[M,K] @ B[K,N], row-major fp32 in/out.
// 128x128 block tile, BK=16, 256 threads = 8 warps (4x2), warp tile 32x64.
// mma.sync.aligned.m16n8k8.row.col.f32.tf32.tf32.f32
// Requires: M%128==0, N%128==0, K%16==0.
// ---------------------------------------------------------------------------
__device__ __forceinline__ unsigned f2tf32(float x) {
    unsigned r;
    asm("cvt.rna.tf32.f32 %0, %1;" : "=r"(r) : "f"(x));
    return r;
}

__device__ __forceinline__ void mma_tf32(float c[4], const unsigned a[4], const unsigned b[2]) {
    asm volatile(
        "mma.sync.aligned.m16n8k8.row.col.f32.tf32.tf32.f32 "
        "{%0,%1,%2,%3}, {%4,%5,%6,%7}, {%8,%9}, {%0,%1,%2,%3};\n"
        : "+f"(c[0]), "+f"(c[1]), "+f"(c[2]), "+f"(c[3])
        : "r"(a[0]), "r"(a[1]), "r"(a[2]), "r"(a[3]), "r"(b[0]), "r"(b[1]));
}

#define TG_PAD 136   // smem row stride (floats): 8*t banks -> conflict-free frags

__global__ __launch_bounds__(256) void tgemm_kernel(
    const float* __restrict__ A, const float* __restrict__ B,
    float* __restrict__ C, int M, int N, int K)
{
    __shared__ unsigned As[16][TG_PAD];   // [k][m] (transposed)
    __shared__ unsigned Bs[16][TG_PAD];   // [k][n]

    const int tid = threadIdx.x;
    const int bx = blockIdx.x, by = blockIdx.y;

    const int lane = tid & 31;
    const int g = lane >> 2;       // 0..7
    const int t = lane & 3;        // 0..3
    const int wid = tid >> 5;
    const int wm = wid >> 1;       // 0..3
    const int wn = wid & 1;        // 0..1
    const int m0 = wm * 32;
    const int n0 = wn * 64;

    // global loaders
    const int arow = tid >> 2;            // 0..63 (+64)
    const int acol = (tid & 3) << 2;      // 0,4,8,12
    const int brow = tid >> 5;            // 0..7 (+8)
    const int bcol = (tid & 31) << 2;     // 0..124

    const float* Ag = A + (size_t)(by * 128 + arow) * K + acol;
    const float* Bg = B + (size_t)brow * N + bx * 128 + bcol;

    float acc[2][8][4];
#pragma unroll
    for (int mt = 0; mt < 2; mt++)
#pragma unroll
        for (int nt = 0; nt < 8; nt++)
#pragma unroll
            for (int r = 0; r < 4; r++) acc[mt][nt][r] = 0.f;

    float4 ra0 = *(const float4*)(Ag);
    float4 ra1 = *(const float4*)(Ag + (size_t)64 * K);
    float4 rb0 = *(const float4*)(Bg);
    float4 rb1 = *(const float4*)(Bg + (size_t)8 * N);

    for (int k0 = 0; k0 < K; k0 += 16) {
        __syncthreads();
        // store (with tf32 round) to smem
        As[acol + 0][arow]      = f2tf32(ra0.x);
        As[acol + 1][arow]      = f2tf32(ra0.y);
        As[acol + 2][arow]      = f2tf32(ra0.z);
        As[acol + 3][arow]      = f2tf32(ra0.w);
        As[acol + 0][arow + 64] = f2tf32(ra1.x);
        As[acol + 1][arow + 64] = f2tf32(ra1.y);
        As[acol + 2][arow + 64] = f2tf32(ra1.z);
        As[acol + 3][arow + 64] = f2tf32(ra1.w);
        {
            uint4 u0 = make_uint4(f2tf32(rb0.x), f2tf32(rb0.y), f2tf32(rb0.z), f2tf32(rb0.w));
            uint4 u1 = make_uint4(f2tf32(rb1.x), f2tf32(rb1.y), f2tf32(rb1.z), f2tf32(rb1.w));
            *(uint4*)&Bs[brow][bcol]     = u0;
            *(uint4*)&Bs[brow + 8][bcol] = u1;
        }
        __syncthreads();

        // prefetch next tile
        if (k0 + 16 < K) {
            ra0 = *(const float4*)(Ag + k0 + 16);
            ra1 = *(const float4*)(Ag + (size_t)64 * K + k0 + 16);
            rb0 = *(const float4*)(Bg + (size_t)(k0 + 16) * N);
            rb1 = *(const float4*)(Bg + (size_t)(k0 + 24) * N);
        }

#pragma unroll
        for (int kk = 0; kk < 16; kk += 8) {
            unsigned a[2][4], bf[8][2];
#pragma unroll
            for (int mt = 0; mt < 2; mt++) {
                int mb = m0 + mt * 16;
                a[mt][0] = As[kk + t][mb + g];
                a[mt][1] = As[kk + t][mb + g + 8];
                a[mt][2] = As[kk + t + 4][mb + g];
                a[mt][3] = As[kk + t + 4][mb + g + 8];
            }
#pragma unroll
            for (int nt = 0; nt < 8; nt++) {
                int nb = n0 + nt * 8;
                bf[nt][0] = Bs[kk + t][nb + g];
                bf[nt][1] = Bs[kk + t + 4][nb + g];
            }
#pragma unroll
            for (int mt = 0; mt < 2; mt++)
#pragma unroll
                for (int nt = 0; nt < 8; nt++)
                    mma_tf32(acc[mt][nt], a[mt], bf[nt]);
        }
    }

    // epilogue
#pragma unroll
    for (int mt = 0; mt < 2; mt++) {
        int r = by * 128 + m0 + mt * 16 + g;
#pragma unroll
        for (int nt = 0; nt < 8; nt++) {
            int c = bx * 128 + n0 + nt * 8 + 2 * t;
            *(float2*)(C + (size_t)r * N + c)       = make_float2(acc[mt][nt][0], acc[mt][nt][1]);
            *(float2*)(C + (size_t)(r + 8) * N + c) = make_float2(acc[mt][nt][2], acc[mt][nt][3]);
        }
    }
}

// ---------------------------------------------------------------------------
// Post-process: RMSNorm + RoPE for Q (16 heads) and K (2 heads), reshape V.
// ---------------------------------------------------------------------------
__global__ __launch_bounds__(256) void qkv_post_kernel(
    const float* __restrict__ cosp, const float* __restrict__ sinp,
    const float* __restrict__ qw, const float* __restrict__ kw)
{
    const int token = blockIdx.x;
    const int unit  = blockIdx.y;
    const int d     = threadIdx.x;
    const int b = token >> 11;      // S = 2048
    const int s = token & 2047;

    __shared__ float sh[DH];
    __shared__ float red[8];

    if (unit < 18) {
        float x;
        const float* w;
        if (unit < 16) {
            x = g_qg[(size_t)token * QGN + unit * 512 + d];
            w = qw;
        } else {
            x = g_k[(size_t)token * KVN + (unit - 16) * 256 + d];
            w = kw;
        }
        float v = x * x;
#pragma unroll
        for (int o = 16; o; o >>= 1) v += __shfl_xor_sync(0xffffffffu, v, o);
        if ((d & 31) == 0) red[d >> 5] = v;
        __syncthreads();
        float tot = 0.f;
#pragma unroll
        for (int i = 0; i < 8; i++) tot += red[i];
        float xn = x * rsqrtf(tot * (1.0f / 256.0f) + 1e-6f) * (1.0f + w[d]);
        sh[d] = xn;
        __syncthreads();
        float out = xn;
        if (d < ROT) {
            float rot = (d < 32) ? -sh[d + 32] : sh[d - 32];
            out = xn * cosp[(size_t)token * ROT + d] + rot * sinp[(size_t)token * ROT + d];
        }
        if (unit < 16)
            g_q[(((size_t)b * NH + unit) * SS + s) * DH + d] = out;
        else
            g_kr[(((size_t)b * NKVH + (unit - 16)) * SS + s) * DH + d] = out;
    } else {
        const int kvh = unit - 18;
        g_vr[(((size_t)b * NKVH + kvh) * SS + s) * DH + d] =
            g_v[(size_t)token * KVN + kvh * 256 + d];
    }
}

// ---------------------------------------------------------------------------
// Flash attention (causal, GQA rep=8), fused gate-sigmoid epilogue.
// 64x64 tiles, D chunked by 64 through SMEM. 256 threads, 4x4 micro-tile.
// ---------------------------------------------------------------------------
#define FA_SMEM_FLOATS (64*65*2 + 64*68*2)

__global__ __launch_bounds__(256) void flash_kernel()
{
    extern __shared__ float sm[];
    float* Qct = sm;                 // [d][row] stride 65
    float* Kct = Qct + 64 * 65;      // [d][key] stride 65
    float* Ps  = Kct + 64 * 65;      // [row][key] stride 68
    float* Vc  = Ps + 64 * 68;       // [key][d] stride 68

    const int tid = threadIdx.x;
    const int tx = tid & 15, ty = tid >> 4;
    const int qt = blockIdx.x;
    const int b  = blockIdx.y >> 4;
    const int h  = blockIdx.y & 15;
    const int kvh = h >> 3;
    const int q0 = qt * 64;

    const float* Qp = g_q  + (((size_t)b * NH + h) * SS + q0) * DH;
    const float* Kp = g_kr + (((size_t)b * NKVH + kvh) * SS) * DH;
    const float* Vp = g_vr + (((size_t)b * NKVH + kvh) * SS) * DH;

    float o[4][16];
    float m[4], l[4];
#pragma unroll
    for (int i = 0; i < 4; i++) {
        m[i] = -1e30f; l[i] = 0.f;
#pragma unroll
        for (int t = 0; t < 16; t++) o[i][t] = 0.f;
    }

    const int lr  = tid >> 4;          // loader row 0..15
    const int ld4 = (tid & 15) * 4;    // loader dim*4

    for (int kt = 0; kt <= qt; kt++) {
        float s[4][4];
#pragma unroll
        for (int i = 0; i < 4; i++)
#pragma unroll
            for (int j = 0; j < 4; j++) s[i][j] = 0.f;

        // ----- scores: S = Q K^T over D=256 in 4 chunks of 64 -----
        for (int c = 0; c < 4; c++) {
            __syncthreads();
#pragma unroll
            for (int it = 0; it < 4; it++) {
                int r = lr + it * 16;
                float4 qv = *(const float4*)(Qp + (size_t)r * DH + c * 64 + ld4);
                Qct[(ld4 + 0) * 65 + r] = qv.x;
                Qct[(ld4 + 1) * 65 + r] = qv.y;
                Qct[(ld4 + 2) * 65 + r] = qv.z;
                Qct[(ld4 + 3) * 65 + r] = qv.w;
                float4 kv = *(const float4*)(Kp + (size_t)(kt * 64 + r) * DH + c * 64 + ld4);
                Kct[(ld4 + 0) * 65 + r] = kv.x;
                Kct[(ld4 + 1) * 65 + r] = kv.y;
                Kct[(ld4 + 2) * 65 + r] = kv.z;
                Kct[(ld4 + 3) * 65 + r] = kv.w;
            }
            __syncthreads();
#pragma unroll 8
            for (int dd = 0; dd < 64; dd++) {
                float a0 = Qct[dd * 65 + ty * 4 + 0];
                float a1 = Qct[dd * 65 + ty * 4 + 1];
                float a2 = Qct[dd * 65 + ty * 4 + 2];
                float a3 = Qct[dd * 65 + ty * 4 + 3];
                float b0 = Kct[dd * 65 + tx * 4 + 0];
                float b1 = Kct[dd * 65 + tx * 4 + 1];
                float b2 = Kct[dd * 65 + tx * 4 + 2];
                float b3 = Kct[dd * 65 + tx * 4 + 3];
                s[0][0] += a0 * b0; s[0][1] += a0 * b1; s[0][2] += a0 * b2; s[0][3] += a0 * b3;
                s[1][0] += a1 * b0; s[1][1] += a1 * b1; s[1][2] += a1 * b2; s[1][3] += a1 * b3;
                s[2][0] += a2 * b0; s[2][1] += a2 * b1; s[2][2] += a2 * b2; s[2][3] += a2 * b3;
                s[3][0] += a3 * b0; s[3][1] += a3 * b1; s[3][2] += a3 * b2; s[3][3] += a3 * b3;
            }
        }

        // ----- scale + causal mask (diag tile only) -----
        const float SCALE = 0.0625f;  // 1/sqrt(256)
        if (kt == qt) {
#pragma unroll
            for (int i = 0; i < 4; i++)
#pragma unroll
                for (int j = 0; j < 4; j++)
                    s[i][j] = (tx * 4 + j > ty * 4 + i) ? -1e30f : s[i][j] * SCALE;
        } else {
#pragma unroll
            for (int i = 0; i < 4; i++)
#pragma unroll
                for (int j = 0; j < 4; j++) s[i][j] *= SCALE;
        }

        // ----- online softmax -----
#pragma unroll
        for (int i = 0; i < 4; i++) {
            float rm = fmaxf(fmaxf(s[i][0], s[i][1]), fmaxf(s[i][2], s[i][3]));
#pragma unroll
            for (int off = 8; off; off >>= 1)
                rm = fmaxf(rm, __shfl_xor_sync(0xffffffffu, rm, off));
            float mn = fmaxf(m[i], rm);
            float alpha = __expf(m[i] - mn);
            m[i] = mn;
            float rs = 0.f;
#pragma unroll
            for (int j = 0; j < 4; j++) { s[i][j] = __expf(s[i][j] - mn); rs += s[i][j]; }
#pragma unroll
            for (int off = 8; off; off >>= 1)
                rs += __shfl_xor_sync(0xffffffffu, rs, off);
            l[i] = l[i] * alpha + rs;
#pragma unroll
            for (int t = 0; t < 16; t++) o[i][t] *= alpha;
            *(float4*)&Ps[(ty * 4 + i) * 68 + tx * 4] =
                make_float4(s[i][0], s[i][1], s[i][2], s[i][3]);
        }

        // ----- O += P V  (V in 4 d-chunks of 64) -----
        for (int c = 0; c < 4; c++) {
            __syncthreads();
#pragma unroll
            for (int it = 0; it < 4; it++) {
                int r = lr + it * 16;
                *(float4*)&Vc[r * 68 + ld4] =
                    *(const float4*)(Vp + (size_t)(kt * 64 + r) * DH + c * 64 + ld4);
            }
            __syncthreads();
#pragma unroll 8
            for (int key = 0; key < 64; key++) {
                float4 v = *(const float4*)&Vc[key * 68 + tx * 4];
#pragma unroll
                for (int i = 0; i < 4; i++) {
                    float p = Ps[(ty * 4 + i) * 68 + key];
                    o[i][c * 4 + 0] += p * v.x;
                    o[i][c * 4 + 1] += p * v.y;
                    o[i][c * 4 + 2] += p * v.z;
                    o[i][c * 4 + 3] += p * v.w;
                }
            }
        }
    }

    // ----- epilogue: /l, * sigmoid(gate), write to attn matrix -----
#pragma unroll
    for (int i = 0; i < 4; i++) {
        int r = q0 + ty * 4 + i;
        size_t token = (size_t)b * SS + r;
        float inv = 1.f / l[i];
#pragma unroll
        for (int c = 0; c < 4; c++) {
            int d = c * 64 + tx * 4;
            float4 g = *(const float4*)(g_qg + token * QGN + h * 512 + 256 + d);
            float4 ov;
            ov.x = o[i][c * 4 + 0] * inv / (1.f + __expf(-g.x));
            ov.y = o[i][c * 4 + 1] * inv / (1.f + __expf(-g.y));
            ov.z = o[i][c * 4 + 2] * inv / (1.f + __expf(-g.z));
            ov.w = o[i][c * 4 + 3] * inv / (1.f + __expf(-g.w));
            *(float4*)(g_attn + token * ODIM + h * 256 + d) = ov;
        }
    }
}

// ---------------------------------------------------------------------------
extern "C" void kernel_launch(void* const* d_in, const int* in_sizes, int n_in,
                              void* d_out, int out_size)
{
    (void)in_sizes; (void)n_in; (void)out_size;
    const float* hs   = (const float*)d_in[0];
    const float* cosp = (const float*)d_in[1];
    const float* sinp = (const float*)d_in[2];
    const float* Wq   = (const float*)d_in[3];
    const float* Wk   = (const float*)d_in[4];
    const float* Wv   = (const float*)d_in[5];
    const float* Wo   = (const float*)d_in[6];
    const float* qw   = (const float*)d_in[7];
    const float* kw   = (const float*)d_in[8];
    float* out = (float*)d_out;

    float *p_qg, *p_k, *p_v, *p_attn;
    cudaGetSymbolAddress((void**)&p_qg,   g_qg);
    cudaGetSymbolAddress((void**)&p_k,    g_k);
    cudaGetSymbolAddress((void**)&p_v,    g_v);
    cudaGetSymbolAddress((void**)&p_attn, g_attn);

    // 1) Projections (tf32 tensor cores)
    tgemm_kernel<<<dim3(QGN / 128, MM / 128), 256>>>(hs, Wq, p_qg, MM, QGN, HID);
    tgemm_kernel<<<dim3(KVN / 128, MM / 128), 256>>>(hs, Wk, p_k,  MM, KVN, HID);
    tgemm_kernel<<<dim3(KVN / 128, MM / 128), 256>>>(hs, Wv, p_v,  MM, KVN, HID);

    // 2) RMSNorm + RoPE + reshape
    qkv_post_kernel<<<dim3(MM, 20), 256>>>(cosp, sinp, qw, kw);

    // 3) Flash attention + gate
    static const int fa_smem = FA_SMEM_FLOATS * (int)sizeof(float);
    cudaFuncSetAttribute(flash_kernel, cudaFuncAttributeMaxDynamicSharedMemorySize, fa_smem);
    flash_kernel<<<dim3(SS / 64, BB * NH), 256, fa_smem>>>();

    // 4) Output projection (tf32 tensor cores)
    tgemm_kernel<<<dim3(HID / 128, MM / 128), 256>>>(p_attn, Wo, out, MM, HID, ODIM);
}

// round 3
// speedup vs baseline: 2.6883x; 1.6974x over previous
#include <cuda_runtime.h>
#include <cuda_bf16.h>
#include <math.h>

// Problem constants
#define BB 2
#define SS 2048
#define HID 2048
#define NH 16
#define NKVH 2
#define DH 256
#define ROT 64
#define MM (BB*SS)          // 4096 tokens
#define QGN (NH*DH*2)       // 8192
#define KVN (NKVH*DH)       // 512
#define ODIM (NH*DH)        // 4096

// Scratch (device globals; allocation-free per harness rules)
__device__ float g_qg[(size_t)MM * QGN];     // [token][h*512 + (0..255 q | 256..511 gate)]
__device__ float g_k [(size_t)MM * KVN];
__device__ float g_v [(size_t)MM * KVN];
__device__ float g_q [(size_t)BB * NH  * SS * DH];   // [b][h][s][d]  (tf32 bits, pre-scaled)
__device__ float g_kr[(size_t)BB * NKVH * SS * DH];  // tf32 bits
__device__ float g_vr[(size_t)BB * NKVH * SS * DH];  // tf32 bits
__device__ float g_attn[(size_t)MM * ODIM];          // [token][h*256+d]

__device__ __forceinline__ unsigned f2tf32(float x) {
    unsigned r;
    asm("cvt.rna.tf32.f32 %0, %1;" : "=r"(r) : "f"(x));
    return r;
}

__device__ __forceinline__ void mma_tf32(float c[4], const unsigned a[4], const unsigned b[2]) {
    asm volatile(
        "mma.sync.aligned.m16n8k8.row.col.f32.tf32.tf32.f32 "
        "{%0,%1,%2,%3}, {%4,%5,%6,%7}, {%8,%9}, {%0,%1,%2,%3};\n"
        : "+f"(c[0]), "+f"(c[1]), "+f"(c[2]), "+f"(c[3])
        : "r"(a[0]), "r"(a[1]), "r"(a[2]), "r"(a[3]), "r"(b[0]), "r"(b[1]));
}

__device__ __forceinline__ void cp16(void* dst, const void* src) {
    unsigned d = (unsigned)__cvta_generic_to_shared(dst);
    asm volatile("cp.async.cg.shared.global [%0], [%1], 16;\n" :: "r"(d), "l"(src));
}
__device__ __forceinline__ void cp_commit() { asm volatile("cp.async.commit_group;\n"); }

// ---------------------------------------------------------------------------
// tf32 tensor-core GEMM v2: cp.async double-buffered, BK=32.
// C[M,N] = A[M,K] @ B[K,N], row-major fp32. 128x128 tile, 256 thr = 8 warps
// (4 wm x 2 wn), warp tile 32x64. Requires M%128==0, N%128==0, K%32==0.
// ---------------------------------------------------------------------------
#define AS_STR 36
#define BS_STR 136

__global__ __launch_bounds__(256) void tgemm_kernel(
    const float* __restrict__ A, const float* __restrict__ B,
    float* __restrict__ C, int M, int N, int K)
{
    __shared__ float As[2][128][AS_STR];   // [m][k]
    __shared__ float Bs[2][32][BS_STR];    // [k][n]

    const int tid = threadIdx.x;
    const int bx = blockIdx.x, by = blockIdx.y;
    const int lane = tid & 31;
    const int g = lane >> 2, t = lane & 3;
    const int wid = tid >> 5;
    const int m0 = (wid >> 1) * 32;
    const int n0 = (wid & 1) * 64;

    const int arow = tid >> 3;            // 0..31 (+32 per it)
    const int acol = (tid & 7) * 4;       // 0..28
    const int brow = tid >> 5;            // 0..7  (+8 per it)
    const int bcol = (tid & 31) * 4;      // 0..124

    const float* Ag = A + (size_t)(by * 128 + arow) * K + acol;
    const float* Bg = B + (size_t)brow * N + bx * 128 + bcol;

    const int nk = K >> 5;

    auto issue = [&](int st, int k0) {
#pragma unroll
        for (int it = 0; it < 4; it++)
            cp16(&As[st][arow + it * 32][acol], Ag + (size_t)it * 32 * K + k0);
#pragma unroll
        for (int it = 0; it < 4; it++)
            cp16(&Bs[st][brow + it * 8][bcol], Bg + (size_t)(k0 + it * 8) * N);
        cp_commit();
    };

    issue(0, 0);
    if (nk > 1) issue(1, 32);

    float acc[2][8][4];
#pragma unroll
    for (int mt = 0; mt < 2; mt++)
#pragma unroll
        for (int nt = 0; nt < 8; nt++)
#pragma unroll
            for (int r = 0; r < 4; r++) acc[mt][nt][r] = 0.f;

    for (int i = 0; i < nk; i++) {
        const int st = i & 1;
        if (i + 1 < nk) asm volatile("cp.async.wait_group 1;\n");
        else            asm volatile("cp.async.wait_group 0;\n");
        __syncthreads();

#pragma unroll
        for (int kk = 0; kk < 32; kk += 8) {
            unsigned a[2][4], bf[8][2];
#pragma unroll
            for (int mt = 0; mt < 2; mt++) {
                const int r = m0 + mt * 16 + g;
                a[mt][0] = f2tf32(As[st][r][kk + t]);
                a[mt][1] = f2tf32(As[st][r + 8][kk + t]);
                a[mt][2] = f2tf32(As[st][r][kk + t + 4]);
                a[mt][3] = f2tf32(As[st][r + 8][kk + t + 4]);
            }
#pragma unroll
            for (int nt = 0; nt < 8; nt++) {
                const int c = n0 + nt * 8 + g;
                bf[nt][0] = f2tf32(Bs[st][kk + t][c]);
                bf[nt][1] = f2tf32(Bs[st][kk + t + 4][c]);
            }
#pragma unroll
            for (int mt = 0; mt < 2; mt++)
#pragma unroll
                for (int nt = 0; nt < 8; nt++)
                    mma_tf32(acc[mt][nt], a[mt], bf[nt]);
        }
        __syncthreads();
        if (i + 2 < nk) issue(st, (i + 2) * 32);
    }

#pragma unroll
    for (int mt = 0; mt < 2; mt++) {
        const int r = by * 128 + m0 + mt * 16 + g;
#pragma unroll
        for (int nt = 0; nt < 8; nt++) {
            const int c = bx * 128 + n0 + nt * 8 + 2 * t;
            *(float2*)(C + (size_t)r * N + c)       = make_float2(acc[mt][nt][0], acc[mt][nt][1]);
            *(float2*)(C + (size_t)(r + 8) * N + c) = make_float2(acc[mt][nt][2], acc[mt][nt][3]);
        }
    }
}

// ---------------------------------------------------------------------------
// Post-process: RMSNorm + RoPE for Q/K, reshape V. Outputs tf32-rounded;
// 1/sqrt(D) folded into q.
// ---------------------------------------------------------------------------
__global__ __launch_bounds__(256) void qkv_post_kernel(
    const float* __restrict__ cosp, const float* __restrict__ sinp,
    const float* __restrict__ qw, const float* __restrict__ kw)
{
    const int token = blockIdx.x;
    const int unit  = blockIdx.y;
    const int d     = threadIdx.x;
    const int b = token >> 11;
    const int s = token & 2047;

    __shared__ float sh[DH];
    __shared__ float red[8];

    if (unit < 18) {
        float x;
        const float* w;
        if (unit < 16) {
            x = g_qg[(size_t)token * QGN + unit * 512 + d];
            w = qw;
        } else {
            x = g_k[(size_t)token * KVN + (unit - 16) * 256 + d];
            w = kw;
        }
        float v = x * x;
#pragma unroll
        for (int o = 16; o; o >>= 1) v += __shfl_xor_sync(0xffffffffu, v, o);
        if ((d & 31) == 0) red[d >> 5] = v;
        __syncthreads();
        float tot = 0.f;
#pragma unroll
        for (int i = 0; i < 8; i++) tot += red[i];
        float xn = x * rsqrtf(tot * (1.0f / 256.0f) + 1e-6f) * (1.0f + w[d]);
        sh[d] = xn;
        __syncthreads();
        float out = xn;
        if (d < ROT) {
            float rot = (d < 32) ? -sh[d + 32] : sh[d - 32];
            out = xn * cosp[(size_t)token * ROT + d] + rot * sinp[(size_t)token * ROT + d];
        }
        if (unit < 16)
            g_q[(((size_t)b * NH + unit) * SS + s) * DH + d] =
                __uint_as_float(f2tf32(out * 0.0625f));
        else
            g_kr[(((size_t)b * NKVH + (unit - 16)) * SS + s) * DH + d] =
                __uint_as_float(f2tf32(out));
    } else {
        const int kvh = unit - 18;
        g_vr[(((size_t)b * NKVH + kvh) * SS + s) * DH + d] =
            __uint_as_float(f2tf32(g_v[(size_t)token * KVN + kvh * 256 + d]));
    }
}

// ---------------------------------------------------------------------------
// Flash attention v2 (tf32 tensor cores). 64x64 tiles, fp32 online softmax,
// fused sigmoid-gate epilogue. 256 threads = 8 warps:
//   QK: warps (wm 0..1) x (wn 0..3): S warp-tile 32 rows x 16 keys
//   PV: same wm rows; warp covers d-cols wn*16..+15 within each 64-d chunk
// ---------------------------------------------------------------------------
#define QS_STR 260
#define KS_STR 68
#define VS_STR 72
#define PS_STR 68
#define FL_SMEM ((64*QS_STR + 64*KS_STR + 64*VS_STR + 64*PS_STR + 512) * 4)

__global__ __launch_bounds__(256) void flash_kernel()
{
    extern __shared__ float sm[];
    float* Qs   = sm;                      // [row][d]   tf32 bits
    float* Ks   = Qs + 64 * QS_STR;        // [key][d]   tf32 bits (64-d chunk)
    float* Vs   = Ks + 64 * KS_STR;        // [key][d]   tf32 bits (64-d chunk)
    float* Ps   = Vs + 64 * VS_STR;        // [row][key] tf32 bits
    float* redm = Ps + 64 * PS_STR;        // [wn][row]
    float* redl = redm + 256;              // [wn][row]

    const int tid = threadIdx.x;
    const int lane = tid & 31;
    const int g = lane >> 2, t = lane & 3;
    const int wid = tid >> 5;
    const int wm = wid >> 2;               // 0..1
    const int wn = wid & 3;                // 0..3

    const int qt = blockIdx.x;
    const int b  = blockIdx.y >> 4;
    const int h  = blockIdx.y & 15;
    const int kvh = h >> 3;
    const int q0 = qt * 64;

    const float* Qp = g_q  + (((size_t)b * NH + h) * SS + q0) * DH;
    const float* Kp = g_kr + ((size_t)b * NKVH + kvh) * SS * DH;
    const float* Vp = g_vr + ((size_t)b * NKVH + kvh) * SS * DH;

    // Load Q block (resident): 64 rows x 256
#pragma unroll
    for (int it = 0; it < 16; it++) {
        const int r = it * 4 + (tid >> 6);
        const int c = (tid & 63) * 4;
        *(float4*)&Qs[r * QS_STR + c] = *(const float4*)(Qp + (size_t)r * DH + c);
    }

    float o[2][8][4];
    float mrun[4], lrun[4];
#pragma unroll
    for (int mt = 0; mt < 2; mt++)
#pragma unroll
        for (int cc = 0; cc < 8; cc++)
#pragma unroll
            for (int r = 0; r < 4; r++) o[mt][cc][r] = 0.f;
#pragma unroll
    for (int i = 0; i < 4; i++) { mrun[i] = -1e30f; lrun[i] = 0.f; }

    for (int kt = 0; kt <= qt; kt++) {
        const float* Kt = Kp + (size_t)(kt * 64) * DH;
        const float* Vt = Vp + (size_t)(kt * 64) * DH;

        float s[2][2][4];
#pragma unroll
        for (int mt = 0; mt < 2; mt++)
#pragma unroll
            for (int nt = 0; nt < 2; nt++)
#pragma unroll
                for (int r = 0; r < 4; r++) s[mt][nt][r] = 0.f;

        // ---- S = Q K^T over D in 4 chunks of 64 ----
        for (int c = 0; c < 4; c++) {
            __syncthreads();
#pragma unroll
            for (int it = 0; it < 4; it++) {
                const int key = it * 16 + (tid >> 4);
                const int col = (tid & 15) * 4;
                *(float4*)&Ks[key * KS_STR + col] =
                    *(const float4*)(Kt + (size_t)key * DH + c * 64 + col);
            }
            __syncthreads();
#pragma unroll
            for (int kk = 0; kk < 64; kk += 8) {
                unsigned a[2][4], bf[2][2];
#pragma unroll
                for (int mt = 0; mt < 2; mt++) {
                    const int r = wm * 32 + mt * 16 + g;
                    const int cbase = c * 64 + kk + t;
                    a[mt][0] = __float_as_uint(Qs[r * QS_STR + cbase]);
                    a[mt][1] = __float_as_uint(Qs[(r + 8) * QS_STR + cbase]);
                    a[mt][2] = __float_as_uint(Qs[r * QS_STR + cbase + 4]);
                    a[mt][3] = __float_as_uint(Qs[(r + 8) * QS_STR + cbase + 4]);
                }
#pragma unroll
                for (int nt = 0; nt < 2; nt++) {
                    const int key = wn * 16 + nt * 8 + g;
                    bf[nt][0] = __float_as_uint(Ks[key * KS_STR + kk + t]);
                    bf[nt][1] = __float_as_uint(Ks[key * KS_STR + kk + t + 4]);
                }
#pragma unroll
                for (int mt = 0; mt < 2; mt++)
#pragma unroll
                    for (int nt = 0; nt < 2; nt++)
                        mma_tf32(s[mt][nt], a[mt], bf[nt]);
            }
        }

        // ---- causal mask (diag tile only; scale pre-folded into q) ----
        if (kt == qt) {
#pragma unroll
            for (int mt = 0; mt < 2; mt++)
#pragma unroll
                for (int nt = 0; nt < 2; nt++)
#pragma unroll
                    for (int r = 0; r < 4; r++) {
                        const int row = wm * 32 + mt * 16 + (r >> 1) * 8 + g;
                        const int col = wn * 16 + nt * 8 + 2 * t + (r & 1);
                        if (col > row) s[mt][nt][r] = -1e30f;
                    }
        }

        // ---- online softmax ----
        float al[4];
#pragma unroll
        for (int mt = 0; mt < 2; mt++)
#pragma unroll
            for (int hh = 0; hh < 2; hh++) {
                float v = fmaxf(fmaxf(s[mt][0][hh * 2], s[mt][0][hh * 2 + 1]),
                                fmaxf(s[mt][1][hh * 2], s[mt][1][hh * 2 + 1]));
                v = fmaxf(v, __shfl_xor_sync(0xffffffffu, v, 1));
                v = fmaxf(v, __shfl_xor_sync(0xffffffffu, v, 2));
                if (t == 0) redm[wn * 64 + wm * 32 + mt * 16 + hh * 8 + g] = v;
            }
        __syncthreads();
#pragma unroll
        for (int mt = 0; mt < 2; mt++)
#pragma unroll
            for (int hh = 0; hh < 2; hh++) {
                const int idx = mt * 2 + hh;
                const int rl = wm * 32 + mt * 16 + hh * 8 + g;
                float tm = fmaxf(fmaxf(redm[rl], redm[64 + rl]),
                                 fmaxf(redm[128 + rl], redm[192 + rl]));
                float mn = fmaxf(mrun[idx], tm);
                al[idx] = __expf(mrun[idx] - mn);
                mrun[idx] = mn;
                float rs = 0.f;
#pragma unroll
                for (int nt = 0; nt < 2; nt++)
#pragma unroll
                    for (int j = 0; j < 2; j++) {
                        float p = __expf(s[mt][nt][hh * 2 + j] - mn);
                        s[mt][nt][hh * 2 + j] = p;
                        rs += p;
                    }
                rs += __shfl_xor_sync(0xffffffffu, rs, 1);
                rs += __shfl_xor_sync(0xffffffffu, rs, 2);
                if (t == 0) redl[wn * 64 + rl] = rs;
            }
        // write P (tf32 bits)
#pragma unroll
        for (int mt = 0; mt < 2; mt++)
#pragma unroll
            for (int nt = 0; nt < 2; nt++) {
                const int r = wm * 32 + mt * 16 + g;
                const int c = wn * 16 + nt * 8 + 2 * t;
                Ps[r * PS_STR + c]           = __uint_as_float(f2tf32(s[mt][nt][0]));
                Ps[r * PS_STR + c + 1]       = __uint_as_float(f2tf32(s[mt][nt][1]));
                Ps[(r + 8) * PS_STR + c]     = __uint_as_float(f2tf32(s[mt][nt][2]));
                Ps[(r + 8) * PS_STR + c + 1] = __uint_as_float(f2tf32(s[mt][nt][3]));
            }
        __syncthreads();
#pragma unroll
        for (int mt = 0; mt < 2; mt++)
#pragma unroll
            for (int hh = 0; hh < 2; hh++) {
                const int idx = mt * 2 + hh;
                const int rl = wm * 32 + mt * 16 + hh * 8 + g;
                float ts = redl[rl] + redl[64 + rl] + redl[128 + rl] + redl[192 + rl];
                lrun[idx] = lrun[idx] * al[idx] + ts;
#pragma unroll
                for (int cc = 0; cc < 8; cc++) {
                    o[mt][cc][hh * 2]     *= al[idx];
                    o[mt][cc][hh * 2 + 1] *= al[idx];
                }
            }

        // ---- O += P V over d in 4 chunks of 64 ----
        for (int c = 0; c < 4; c++) {
            if (c) __syncthreads();
#pragma unroll
            for (int it = 0; it < 4; it++) {
                const int key = it * 16 + (tid >> 4);
                const int col = (tid & 15) * 4;
                *(float4*)&Vs[key * VS_STR + col] =
                    *(const float4*)(Vt + (size_t)key * DH + c * 64 + col);
            }
            __syncthreads();
#pragma unroll
            for (int kk = 0; kk < 64; kk += 8) {
                unsigned a[2][4], bf[2][2];
#pragma unroll
                for (int mt = 0; mt < 2; mt++) {
                    const int r = wm * 32 + mt * 16 + g;
                    a[mt][0] = __float_as_uint(Ps[r * PS_STR + kk + t]);
                    a[mt][1] = __float_as_uint(Ps[(r + 8) * PS_STR + kk + t]);
                    a[mt][2] = __float_as_uint(Ps[r * PS_STR + kk + t + 4]);
                    a[mt][3] = __float_as_uint(Ps[(r + 8) * PS_STR + kk + t + 4]);
                }
#pragma unroll
                for (int nt = 0; nt < 2; nt++) {
                    const int dc = wn * 16 + nt * 8 + g;
                    bf[nt][0] = __float_as_uint(Vs[(kk + t) * VS_STR + dc]);
                    bf[nt][1] = __float_as_uint(Vs[(kk + t + 4) * VS_STR + dc]);
                }
#pragma unroll
                for (int mt = 0; mt < 2; mt++)
#pragma unroll
                    for (int nt = 0; nt < 2; nt++)
                        mma_tf32(o[mt][c * 2 + nt], a[mt], bf[nt]);
            }
        }
    }

    // ---- epilogue: /l, * sigmoid(gate) ----
#pragma unroll
    for (int mt = 0; mt < 2; mt++)
#pragma unroll
        for (int hh = 0; hh < 2; hh++) {
            const int idx = mt * 2 + hh;
            const int row = q0 + wm * 32 + mt * 16 + hh * 8 + g;
            const size_t token = (size_t)b * SS + row;
            const float inv = 1.f / lrun[idx];
#pragma unroll
            for (int cc = 0; cc < 8; cc++) {
                const int col = (cc >> 1) * 64 + wn * 16 + (cc & 1) * 8 + 2 * t;
                float2 gt = *(const float2*)(g_qg + token * QGN + h * 512 + 256 + col);
                float2 ov;
                ov.x = o[mt][cc][hh * 2]     * inv / (1.f + __expf(-gt.x));
                ov.y = o[mt][cc][hh * 2 + 1] * inv / (1.f + __expf(-gt.y));
                *(float2*)(g_attn + token * ODIM + h * 256 + col) = ov;
            }
        }
}

// ---------------------------------------------------------------------------
extern "C" void kernel_launch(void* const* d_in, const int* in_sizes, int n_in,
                              void* d_out, int out_size)
{
    (void)in_sizes; (void)n_in; (void)out_size;
    const float* hs   = (const float*)d_in[0];
    const float* cosp = (const float*)d_in[1];
    const float* sinp = (const float*)d_in[2];
    const float* Wq   = (const float*)d_in[3];
    const float* Wk   = (const float*)d_in[4];
    const float* Wv   = (const float*)d_in[5];
    const float* Wo   = (const float*)d_in[6];
    const float* qw   = (const float*)d_in[7];
    const float* kw   = (const float*)d_in[8];
    float* out = (float*)d_out;

    float *p_qg, *p_k, *p_v, *p_attn;
    cudaGetSymbolAddress((void**)&p_qg,   g_qg);
    cudaGetSymbolAddress((void**)&p_k,    g_k);
    cudaGetSymbolAddress((void**)&p_v,    g_v);
    cudaGetSymbolAddress((void**)&p_attn, g_attn);

    // 1) Projections (tf32 tensor cores, cp.async pipelined)
    tgemm_kernel<<<dim3(QGN / 128, MM / 128), 256>>>(hs, Wq, p_qg, MM, QGN, HID);
    tgemm_kernel<<<dim3(KVN / 128, MM / 128), 256>>>(hs, Wk, p_k,  MM, KVN, HID);
    tgemm_kernel<<<dim3(KVN / 128, MM / 128), 256>>>(hs, Wv, p_v,  MM, KVN, HID);

    // 2) RMSNorm + RoPE + reshape (tf32-rounded outputs, scale folded)
    qkv_post_kernel<<<dim3(MM, 20), 256>>>(cosp, sinp, qw, kw);

    // 3) Flash attention (tf32 mma) + gate
    cudaFuncSetAttribute(flash_kernel, cudaFuncAttributeMaxDynamicSharedMemorySize, FL_SMEM);
    flash_kernel<<<dim3(SS / 64, BB * NH), 256, FL_SMEM>>>();

    // 4) Output projection
    tgemm_kernel<<<dim3(HID / 128, MM / 128), 256>>>(p_attn, Wo, out, MM, HID, ODIM);
}

// round 4
// speedup vs baseline: 3.1872x; 1.1856x over previous
#include <cuda_runtime.h>
#include <cuda_bf16.h>
#include <math.h>

// Problem constants
#define BB 2
#define SS 2048
#define HID 2048
#define NH 16
#define NKVH 2
#define DH 256
#define ROT 64
#define MM (BB*SS)          // 4096 tokens
#define QGN (NH*DH*2)       // 8192
#define KVN (NKVH*DH)       // 512
#define ODIM (NH*DH)        // 4096

// Scratch (device globals)
__device__ float g_hs  [(size_t)MM * HID];          // tf32-rounded hidden states
__device__ float g_wqt [(size_t)QGN * HID];         // Wq^T  [N][K] tf32
__device__ float g_wkvt[(size_t)(2*KVN) * HID];     // [Wk^T; Wv^T] tf32
__device__ float g_wot [(size_t)HID * ODIM];        // Wo^T tf32
__device__ float g_qg  [(size_t)MM * QGN];          // [token][h*512 + (q|gate)]
__device__ float g_kv  [(size_t)MM * 2*KVN];        // [token][k 0..511 | v 512..1023]
__device__ float g_q   [(size_t)BB * NH  * SS * DH];   // [b][h][s][d] tf32, scale folded
__device__ float g_kr  [(size_t)BB * NKVH * SS * DH];  // [b][kvh][s][d] tf32
__device__ float g_vr  [(size_t)BB * NKVH * DH * SS];  // [b][kvh][d][s] tf32 (TRANSPOSED)
__device__ float g_attn[(size_t)MM * ODIM];            // tf32-rounded

__device__ __forceinline__ unsigned f2tf32(float x) {
    unsigned r;
    asm("cvt.rna.tf32.f32 %0, %1;" : "=r"(r) : "f"(x));
    return r;
}

__device__ __forceinline__ void mma_tf32(float c[4], const unsigned a[4], const unsigned* b) {
    asm volatile(
        "mma.sync.aligned.m16n8k8.row.col.f32.tf32.tf32.f32 "
        "{%0,%1,%2,%3}, {%4,%5,%6,%7}, {%8,%9}, {%0,%1,%2,%3};\n"
        : "+f"(c[0]), "+f"(c[1]), "+f"(c[2]), "+f"(c[3])
        : "r"(a[0]), "r"(a[1]), "r"(a[2]), "r"(a[3]), "r"(b[0]), "r"(b[1]));
}

__device__ __forceinline__ void ldsm4(unsigned r[4], const float* p) {
    unsigned a = (unsigned)__cvta_generic_to_shared(p);
    asm volatile("ldmatrix.sync.aligned.m8n8.x4.shared.b16 {%0,%1,%2,%3}, [%4];\n"
                 : "=r"(r[0]), "=r"(r[1]), "=r"(r[2]), "=r"(r[3]) : "r"(a));
}

__device__ __forceinline__ void cp16(void* dst, const void* src) {
    unsigned d = (unsigned)__cvta_generic_to_shared(dst);
    asm volatile("cp.async.cg.shared.global [%0], [%1], 16;\n" :: "r"(d), "l"(src));
}
__device__ __forceinline__ void cp_commit() { asm volatile("cp.async.commit_group;\n"); }

// ---------------------------------------------------------------------------
// Prep: elementwise tf32 round (float4 grid-stride)
// ---------------------------------------------------------------------------
__global__ __launch_bounds__(256) void round_kernel(const float* __restrict__ src,
                                                    float* __restrict__ dst, int n4)
{
    for (int i = blockIdx.x * 256 + threadIdx.x; i < n4; i += gridDim.x * 256) {
        float4 v = ((const float4*)src)[i];
        uint4 u = make_uint4(f2tf32(v.x), f2tf32(v.y), f2tf32(v.z), f2tf32(v.w));
        ((uint4*)dst)[i] = u;
    }
}

// ---------------------------------------------------------------------------
// Prep: transpose + tf32 round. src [R][C] -> dst [C][R]. R,C multiples of 32.
// ---------------------------------------------------------------------------
__global__ __launch_bounds__(256) void transpose_round_kernel(
    const float* __restrict__ src, float* __restrict__ dst, int R, int C)
{
    __shared__ float t[32][33];
    const int x = blockIdx.x * 32 + threadIdx.x;
    const int y0 = blockIdx.y * 32;
#pragma unroll
    for (int i = 0; i < 32; i += 8)
        t[threadIdx.y + i][threadIdx.x] = src[(size_t)(y0 + threadIdx.y + i) * C + x];
    __syncthreads();
    const int nx = blockIdx.y * 32 + threadIdx.x;
    const int ny0 = blockIdx.x * 32;
#pragma unroll
    for (int i = 0; i < 32; i += 8)
        dst[(size_t)(ny0 + threadIdx.y + i) * R + nx] =
            __uint_as_float(f2tf32(t[threadIdx.x][threadIdx.y + i]));
}

// ---------------------------------------------------------------------------
// tf32 tensor-core GEMM v3: A [M][K] (tf32 bits), Bt [N][K] (tf32 bits),
// C[M][N] fp32. cp.async double-buffered BK=32, ldmatrix fragments, no cvt.
// 128x128 tile, 256 thr = 8 warps (4 wm x 2 wn), warp 32x64.
// ---------------------------------------------------------------------------
#define GS_STR 36

__global__ __launch_bounds__(256) void tgemm_kernel(
    const float* __restrict__ A, const float* __restrict__ Bt,
    float* __restrict__ C, int M, int N, int K)
{
    extern __shared__ float gsm[];
    float* As = gsm;                         // [2][128][GS_STR]
    float* Bs = gsm + 2 * 128 * GS_STR;      // [2][128][GS_STR]

    const int tid = threadIdx.x;
    const int bx = blockIdx.x, by = blockIdx.y;
    const int lane = tid & 31;
    const int g = lane >> 2, t = lane & 3;
    const int wid = tid >> 5;
    const int m0 = (wid >> 1) * 32;
    const int n0 = (wid & 1) * 64;

    // ldmatrix per-lane offsets
    const int a_row = ((lane >> 3) & 1) * 8 + (lane & 7);
    const int a_kw  = (lane >> 4) * 4;
    const int b_row = ((lane >> 4) & 1) * 8 + (lane & 7);
    const int b_kw  = ((lane >> 3) & 1) * 4;

    // loaders: 1024 cp16 per tile per operand -> 4 per thread
    const int lrow = tid >> 1;               // 0..127 (x2? no: idx pattern below)

    const int nk = K >> 5;

    auto issue = [&](int st, int k0) {
        float* Ad = As + (size_t)st * 128 * GS_STR;
        float* Bd = Bs + (size_t)st * 128 * GS_STR;
#pragma unroll
        for (int it = 0; it < 4; it++) {
            int idx = tid + it * 256;        // 0..1023
            int row = idx >> 3;
            int cw  = (idx & 7) * 4;
            cp16(Ad + row * GS_STR + cw, A  + (size_t)(by * 128 + row) * K + k0 + cw);
            cp16(Bd + row * GS_STR + cw, Bt + (size_t)(bx * 128 + row) * K + k0 + cw);
        }
        cp_commit();
    };
    (void)lrow;

    issue(0, 0);
    if (nk > 1) issue(1, 32);

    float acc[2][8][4];
#pragma unroll
    for (int mt = 0; mt < 2; mt++)
#pragma unroll
        for (int nt = 0; nt < 8; nt++)
#pragma unroll
            for (int r = 0; r < 4; r++) acc[mt][nt][r] = 0.f;

    for (int i = 0; i < nk; i++) {
        const int st = i & 1;
        float* Ad = As + (size_t)st * 128 * GS_STR;
        float* Bd = Bs + (size_t)st * 128 * GS_STR;
        if (i + 1 < nk) asm volatile("cp.async.wait_group 1;\n");
        else            asm volatile("cp.async.wait_group 0;\n");
        __syncthreads();

#pragma unroll
        for (int kk = 0; kk < 32; kk += 8) {
            unsigned a[2][4], bfr[4][4];
            ldsm4(a[0], Ad + (m0 + a_row)      * GS_STR + kk + a_kw);
            ldsm4(a[1], Ad + (m0 + 16 + a_row) * GS_STR + kk + a_kw);
#pragma unroll
            for (int p = 0; p < 4; p++)
                ldsm4(bfr[p], Bd + (n0 + p * 16 + b_row) * GS_STR + kk + b_kw);
#pragma unroll
            for (int mt = 0; mt < 2; mt++)
#pragma unroll
                for (int nt = 0; nt < 8; nt++)
                    mma_tf32(acc[mt][nt], a[mt], &bfr[nt >> 1][(nt & 1) * 2]);
        }
        __syncthreads();
        if (i + 2 < nk) issue(st, (i + 2) * 32);
    }

#pragma unroll
    for (int mt = 0; mt < 2; mt++) {
        const int r = by * 128 + m0 + mt * 16 + g;
#pragma unroll
        for (int nt = 0; nt < 8; nt++) {
            const int c = bx * 128 + n0 + nt * 8 + 2 * t;
            *(float2*)(C + (size_t)r * N + c)       = make_float2(acc[mt][nt][0], acc[mt][nt][1]);
            *(float2*)(C + (size_t)(r + 8) * N + c) = make_float2(acc[mt][nt][2], acc[mt][nt][3]);
        }
    }
}
#define TG_SMEM (2 * 128 * GS_STR * 2 * (int)sizeof(float))

// ---------------------------------------------------------------------------
// Post-process: RMSNorm + RoPE for Q/K, V transpose. tf32 outputs, scale folded.
// ---------------------------------------------------------------------------
__global__ __launch_bounds__(256) void qkv_post_kernel(
    const float* __restrict__ cosp, const float* __restrict__ sinp,
    const float* __restrict__ qw, const float* __restrict__ kw)
{
    const int token = blockIdx.x;
    const int unit  = blockIdx.y;
    const int d     = threadIdx.x;
    const int b = token >> 11;
    const int s = token & 2047;

    __shared__ float sh[DH];
    __shared__ float red[8];

    if (unit < 18) {
        float x;
        const float* w;
        if (unit < 16) {
            x = g_qg[(size_t)token * QGN + unit * 512 + d];
            w = qw;
        } else {
            x = g_kv[(size_t)token * (2*KVN) + (unit - 16) * 256 + d];
            w = kw;
        }
        float v = x * x;
#pragma unroll
        for (int o = 16; o; o >>= 1) v += __shfl_xor_sync(0xffffffffu, v, o);
        if ((d & 31) == 0) red[d >> 5] = v;
        __syncthreads();
        float tot = 0.f;
#pragma unroll
        for (int i = 0; i < 8; i++) tot += red[i];
        float xn = x * rsqrtf(tot * (1.0f / 256.0f) + 1e-6f) * (1.0f + w[d]);
        sh[d] = xn;
        __syncthreads();
        float out = xn;
        if (d < ROT) {
            float rot = (d < 32) ? -sh[d + 32] : sh[d - 32];
            out = xn * cosp[(size_t)token * ROT + d] + rot * sinp[(size_t)token * ROT + d];
        }
        if (unit < 16)
            g_q[(((size_t)b * NH + unit) * SS + s) * DH + d] =
                __uint_as_float(f2tf32(out * 0.0625f));
        else
            g_kr[(((size_t)b * NKVH + (unit - 16)) * SS + s) * DH + d] =
                __uint_as_float(f2tf32(out));
    } else {
        const int kvh = unit - 18;
        // transposed store: [b][kvh][d][s]
        g_vr[(((size_t)b * NKVH + kvh) * DH + d) * SS + s] =
            __uint_as_float(f2tf32(g_kv[(size_t)token * (2*KVN) + 512 + kvh * 256 + d]));
    }
}

// ---------------------------------------------------------------------------
// Flash attention v3 (tf32 mma + ldmatrix). 64x64 tiles, fp32 online softmax,
// fused sigmoid-gate epilogue (tf32-rounded output for the O-projection).
// 8 warps: wm in {0,1} (32 q-rows), wn in {0..3} (16 keys / 16 d-cols).
// ---------------------------------------------------------------------------
#define QS_STR 260
#define KS_STR 68
#define VS_STR 68
#define PS_STR 68
#define FL_SMEM ((64*QS_STR + 64*KS_STR + 64*VS_STR + 64*PS_STR + 512) * 4)

__global__ __launch_bounds__(256) void flash_kernel()
{
    extern __shared__ float sm[];
    float* Qs   = sm;                      // [row][d]   tf32 bits
    float* Ks   = Qs + 64 * QS_STR;        // [key][d]   (64-d chunk)
    float* Vs   = Ks + 64 * KS_STR;        // [d][key]   (64-d chunk, TRANSPOSED)
    float* Ps   = Vs + 64 * VS_STR;        // [row][key] tf32 bits
    float* redm = Ps + 64 * PS_STR;        // [wn][row]
    float* redl = redm + 256;              // [wn][row]

    const int tid = threadIdx.x;
    const int lane = tid & 31;
    const int g = lane >> 2, t = lane & 3;
    const int wid = tid >> 5;
    const int wm = wid >> 2;               // 0..1
    const int wn = wid & 3;                // 0..3

    const int a_row = ((lane >> 3) & 1) * 8 + (lane & 7);
    const int a_kw  = (lane >> 4) * 4;
    const int b_row = ((lane >> 4) & 1) * 8 + (lane & 7);
    const int b_kw  = ((lane >> 3) & 1) * 4;

    const int qt = blockIdx.x;
    const int b  = blockIdx.y >> 4;
    const int h  = blockIdx.y & 15;
    const int kvh = h >> 3;
    const int q0 = qt * 64;

    const float* Qp = g_q  + (((size_t)b * NH + h) * SS + q0) * DH;
    const float* Kp = g_kr + ((size_t)b * NKVH + kvh) * SS * DH;
    const float* VpT = g_vr + ((size_t)b * NKVH + kvh) * DH * SS;

    // Load Q block (resident): 64 rows x 256
#pragma unroll
    for (int it = 0; it < 16; it++) {
        const int r = it * 4 + (tid >> 6);
        const int c = (tid & 63) * 4;
        *(float4*)&Qs[r * QS_STR + c] = *(const float4*)(Qp + (size_t)r * DH + c);
    }

    float o[2][8][4];
    float mrun[4], lrun[4];
#pragma unroll
    for (int mt = 0; mt < 2; mt++)
#pragma unroll
        for (int cc = 0; cc < 8; cc++)
#pragma unroll
            for (int r = 0; r < 4; r++) o[mt][cc][r] = 0.f;
#pragma unroll
    for (int i = 0; i < 4; i++) { mrun[i] = -1e30f; lrun[i] = 0.f; }

    for (int kt = 0; kt <= qt; kt++) {
        const float* Kt = Kp + (size_t)(kt * 64) * DH;

        float s[2][2][4];
#pragma unroll
        for (int mt = 0; mt < 2; mt++)
#pragma unroll
            for (int nt = 0; nt < 2; nt++)
#pragma unroll
                for (int r = 0; r < 4; r++) s[mt][nt][r] = 0.f;

        // ---- S = Q K^T over D in 4 chunks of 64 ----
        for (int c = 0; c < 4; c++) {
            __syncthreads();
#pragma unroll
            for (int it = 0; it < 4; it++) {
                const int key = it * 16 + (tid >> 4);
                const int col = (tid & 15) * 4;
                *(float4*)&Ks[key * KS_STR + col] =
                    *(const float4*)(Kt + (size_t)key * DH + c * 64 + col);
            }
            __syncthreads();
#pragma unroll
            for (int kk = 0; kk < 64; kk += 8) {
                unsigned a[2][4], bq[4];
                ldsm4(a[0], Qs + (wm * 32 + a_row)      * QS_STR + c * 64 + kk + a_kw);
                ldsm4(a[1], Qs + (wm * 32 + 16 + a_row) * QS_STR + c * 64 + kk + a_kw);
                ldsm4(bq,   Ks + (wn * 16 + b_row)      * KS_STR + kk + b_kw);
#pragma unroll
                for (int mt = 0; mt < 2; mt++)
#pragma unroll
                    for (int nt = 0; nt < 2; nt++)
                        mma_tf32(s[mt][nt], a[mt], &bq[nt * 2]);
            }
        }

        // ---- causal mask (diag tile only; scale pre-folded into q) ----
        if (kt == qt) {
#pragma unroll
            for (int mt = 0; mt < 2; mt++)
#pragma unroll
                for (int nt = 0; nt < 2; nt++)
#pragma unroll
                    for (int r = 0; r < 4; r++) {
                        const int row = wm * 32 + mt * 16 + (r >> 1) * 8 + g;
                        const int col = wn * 16 + nt * 8 + 2 * t + (r & 1);
                        if (col > row) s[mt][nt][r] = -1e30f;
                    }
        }

        // ---- online softmax ----
        float al[4];
#pragma unroll
        for (int mt = 0; mt < 2; mt++)
#pragma unroll
            for (int hh = 0; hh < 2; hh++) {
                float v = fmaxf(fmaxf(s[mt][0][hh * 2], s[mt][0][hh * 2 + 1]),
                                fmaxf(s[mt][1][hh * 2], s[mt][1][hh * 2 + 1]));
                v = fmaxf(v, __shfl_xor_sync(0xffffffffu, v, 1));
                v = fmaxf(v, __shfl_xor_sync(0xffffffffu, v, 2));
                if (t == 0) redm[wn * 64 + wm * 32 + mt * 16 + hh * 8 + g] = v;
            }
        __syncthreads();
#pragma unroll
        for (int mt = 0; mt < 2; mt++)
#pragma unroll
            for (int hh = 0; hh < 2; hh++) {
                const int idx = mt * 2 + hh;
                const int rl = wm * 32 + mt * 16 + hh * 8 + g;
                float tm = fmaxf(fmaxf(redm[rl], redm[64 + rl]),
                                 fmaxf(redm[128 + rl], redm[192 + rl]));
                float mn = fmaxf(mrun[idx], tm);
                al[idx] = __expf(mrun[idx] - mn);
                mrun[idx] = mn;
                float rs = 0.f;
#pragma unroll
                for (int nt = 0; nt < 2; nt++)
#pragma unroll
                    for (int j = 0; j < 2; j++) {
                        float p = __expf(s[mt][nt][hh * 2 + j] - mn);
                        s[mt][nt][hh * 2 + j] = p;
                        rs += p;
                    }
                rs += __shfl_xor_sync(0xffffffffu, rs, 1);
                rs += __shfl_xor_sync(0xffffffffu, rs, 2);
                if (t == 0) redl[wn * 64 + rl] = rs;
            }
        // write P (tf32 bits)
#pragma unroll
        for (int mt = 0; mt < 2; mt++)
#pragma unroll
            for (int nt = 0; nt < 2; nt++) {
                const int r = wm * 32 + mt * 16 + g;
                const int c = wn * 16 + nt * 8 + 2 * t;
                Ps[r * PS_STR + c]           = __uint_as_float(f2tf32(s[mt][nt][0]));
                Ps[r * PS_STR + c + 1]       = __uint_as_float(f2tf32(s[mt][nt][1]));
                Ps[(r + 8) * PS_STR + c]     = __uint_as_float(f2tf32(s[mt][nt][2]));
                Ps[(r + 8) * PS_STR + c + 1] = __uint_as_float(f2tf32(s[mt][nt][3]));
            }
        __syncthreads();
#pragma unroll
        for (int mt = 0; mt < 2; mt++)
#pragma unroll
            for (int hh = 0; hh < 2; hh++) {
                const int idx = mt * 2 + hh;
                const int rl = wm * 32 + mt * 16 + hh * 8 + g;
                float ts = redl[rl] + redl[64 + rl] + redl[128 + rl] + redl[192 + rl];
                lrun[idx] = lrun[idx] * al[idx] + ts;
#pragma unroll
                for (int cc = 0; cc < 8; cc++) {
                    o[mt][cc][hh * 2]     *= al[idx];
                    o[mt][cc][hh * 2 + 1] *= al[idx];
                }
            }

        // ---- O += P V over d in 4 chunks of 64 (Vs = [d][key]) ----
        for (int c = 0; c < 4; c++) {
            if (c) __syncthreads();
#pragma unroll
            for (int it = 0; it < 4; it++) {
                const int dl = it * 16 + (tid >> 4);
                const int key = (tid & 15) * 4;
                *(float4*)&Vs[dl * VS_STR + key] =
                    *(const float4*)(VpT + (size_t)(c * 64 + dl) * SS + kt * 64 + key);
            }
            __syncthreads();
#pragma unroll
            for (int kk = 0; kk < 64; kk += 8) {
                unsigned a[2][4], bv[4];
                ldsm4(a[0], Ps + (wm * 32 + a_row)      * PS_STR + kk + a_kw);
                ldsm4(a[1], Ps + (wm * 32 + 16 + a_row) * PS_STR + kk + a_kw);
                ldsm4(bv,   Vs + (wn * 16 + b_row)      * VS_STR + kk + b_kw);
#pragma unroll
                for (int mt = 0; mt < 2; mt++)
#pragma unroll
                    for (int nt = 0; nt < 2; nt++)
                        mma_tf32(o[mt][c * 2 + nt], a[mt], &bv[nt * 2]);
            }
        }
    }

    // ---- epilogue: /l, * sigmoid(gate), tf32-round for O-projection ----
#pragma unroll
    for (int mt = 0; mt < 2; mt++)
#pragma unroll
        for (int hh = 0; hh < 2; hh++) {
            const int idx = mt * 2 + hh;
            const int row = q0 + wm * 32 + mt * 16 + hh * 8 + g;
            const size_t token = (size_t)b * SS + row;
            const float inv = 1.f / lrun[idx];
#pragma unroll
            for (int cc = 0; cc < 8; cc++) {
                const int col = (cc >> 1) * 64 + wn * 16 + (cc & 1) * 8 + 2 * t;
                float2 gt = *(const float2*)(g_qg + token * QGN + h * 512 + 256 + col);
                unsigned ox = f2tf32(o[mt][cc][hh * 2]     * inv / (1.f + __expf(-gt.x)));
                unsigned oy = f2tf32(o[mt][cc][hh * 2 + 1] * inv / (1.f + __expf(-gt.y)));
                *(uint2*)(g_attn + token * ODIM + h * 256 + col) = make_uint2(ox, oy);
            }
        }
}

// ---------------------------------------------------------------------------
extern "C" void kernel_launch(void* const* d_in, const int* in_sizes, int n_in,
                              void* d_out, int out_size)
{
    (void)in_sizes; (void)n_in; (void)out_size;
    const float* hs   = (const float*)d_in[0];
    const float* cosp = (const float*)d_in[1];
    const float* sinp = (const float*)d_in[2];
    const float* Wq   = (const float*)d_in[3];
    const float* Wk   = (const float*)d_in[4];
    const float* Wv   = (const float*)d_in[5];
    const float* Wo   = (const float*)d_in[6];
    const float* qw   = (const float*)d_in[7];
    const float* kw   = (const float*)d_in[8];
    float* out = (float*)d_out;

    float *p_hs, *p_wqt, *p_wkvt, *p_wot, *p_qg, *p_kv, *p_attn;
    cudaGetSymbolAddress((void**)&p_hs,   g_hs);
    cudaGetSymbolAddress((void**)&p_wqt,  g_wqt);
    cudaGetSymbolAddress((void**)&p_wkvt, g_wkvt);
    cudaGetSymbolAddress((void**)&p_wot,  g_wot);
    cudaGetSymbolAddress((void**)&p_qg,   g_qg);
    cudaGetSymbolAddress((void**)&p_kv,   g_kv);
    cudaGetSymbolAddress((void**)&p_attn, g_attn);

    // 0) Prep: round hs; transpose+round weights
    round_kernel<<<2048, 256>>>(hs, p_hs, MM * HID / 4);
    transpose_round_kernel<<<dim3(QGN / 32, HID / 32), dim3(32, 8)>>>(Wq, p_wqt, HID, QGN);
    transpose_round_kernel<<<dim3(KVN / 32, HID / 32), dim3(32, 8)>>>(Wk, p_wkvt, HID, KVN);
    transpose_round_kernel<<<dim3(KVN / 32, HID / 32), dim3(32, 8)>>>(Wv, p_wkvt + (size_t)KVN * HID, HID, KVN);
    transpose_round_kernel<<<dim3(HID / 32, ODIM / 32), dim3(32, 8)>>>(Wo, p_wot, ODIM, HID);

    // 1) Projections (tf32 mma, ldmatrix, cp.async)
    cudaFuncSetAttribute(tgemm_kernel, cudaFuncAttributeMaxDynamicSharedMemorySize, TG_SMEM);
    tgemm_kernel<<<dim3(QGN / 128, MM / 128), 256, TG_SMEM>>>(p_hs, p_wqt, p_qg, MM, QGN, HID);
    tgemm_kernel<<<dim3(2*KVN / 128, MM / 128), 256, TG_SMEM>>>(p_hs, p_wkvt, p_kv, MM, 2*KVN, HID);

    // 2) RMSNorm + RoPE + V transpose
    qkv_post_kernel<<<dim3(MM, 20), 256>>>(cosp, sinp, qw, kw);

    // 3) Flash attention + gate
    cudaFuncSetAttribute(flash_kernel, cudaFuncAttributeMaxDynamicSharedMemorySize, FL_SMEM);
    flash_kernel<<<dim3(SS / 64, BB * NH), 256, FL_SMEM>>>();

    // 4) Output projection
    tgemm_kernel<<<dim3(HID / 128, MM / 128), 256, TG_SMEM>>>(p_attn, p_wot, out, MM, HID, ODIM);
}

// round 5
// speedup vs baseline: 3.3533x; 1.0521x over previous
#include <cuda_runtime.h>
#include <cuda_bf16.h>
#include <math.h>

// Problem constants
#define BB 2
#define SS 2048
#define HID 2048
#define NH 16
#define NKVH 2
#define DH 256
#define ROT 64
#define MM (BB*SS)          // 4096 tokens
#define QGN (NH*DH*2)       // 8192
#define KVN (NKVH*DH)       // 512
#define ODIM (NH*DH)        // 4096

// Scratch (device globals)
__device__ float g_hs  [(size_t)MM * HID];          // tf32-rounded hidden states
__device__ float g_wqt [(size_t)QGN * HID];         // Wq^T  [N][K] tf32
__device__ float g_wkvt[(size_t)(2*KVN) * HID];     // [Wk^T; Wv^T] tf32
__device__ float g_wot [(size_t)HID * ODIM];        // Wo^T tf32
__device__ float g_qg  [(size_t)MM * QGN];          // [token][h*512 + (q|gate)]
__device__ float g_kv  [(size_t)MM * 2*KVN];        // [token][k | v]
__device__ float g_q   [(size_t)BB * NH  * SS * DH];   // [b][h][s][d] tf32, scale folded
__device__ float g_kr  [(size_t)BB * NKVH * SS * DH];  // [b][kvh][s][d] tf32
__device__ float g_vr  [(size_t)BB * NKVH * DH * SS];  // [b][kvh][d][s] tf32 (TRANSPOSED)
__device__ float g_attn[(size_t)MM * ODIM];            // tf32-rounded

__device__ __forceinline__ unsigned f2tf32(float x) {
    unsigned r;
    asm("cvt.rna.tf32.f32 %0, %1;" : "=r"(r) : "f"(x));
    return r;
}

__device__ __forceinline__ void mma_tf32(float c[4], const unsigned a[4], const unsigned* b) {
    asm volatile(
        "mma.sync.aligned.m16n8k8.row.col.f32.tf32.tf32.f32 "
        "{%0,%1,%2,%3}, {%4,%5,%6,%7}, {%8,%9}, {%0,%1,%2,%3};\n"
        : "+f"(c[0]), "+f"(c[1]), "+f"(c[2]), "+f"(c[3])
        : "r"(a[0]), "r"(a[1]), "r"(a[2]), "r"(a[3]), "r"(b[0]), "r"(b[1]));
}

__device__ __forceinline__ void ldsm4(unsigned r[4], const float* p) {
    unsigned a = (unsigned)__cvta_generic_to_shared(p);
    asm volatile("ldmatrix.sync.aligned.m8n8.x4.shared.b16 {%0,%1,%2,%3}, [%4];\n"
                 : "=r"(r[0]), "=r"(r[1]), "=r"(r[2]), "=r"(r[3]) : "r"(a));
}

__device__ __forceinline__ void cp16(void* dst, const void* src) {
    unsigned d = (unsigned)__cvta_generic_to_shared(dst);
    asm volatile("cp.async.cg.shared.global [%0], [%1], 16;\n" :: "r"(d), "l"(src));
}
__device__ __forceinline__ void cp_commit() { asm volatile("cp.async.commit_group;\n"); }

// ---------------------------------------------------------------------------
// Prep kernels
// ---------------------------------------------------------------------------
__global__ __launch_bounds__(256) void round_kernel(const float* __restrict__ src,
                                                    float* __restrict__ dst, int n4)
{
    for (int i = blockIdx.x * 256 + threadIdx.x; i < n4; i += gridDim.x * 256) {
        float4 v = ((const float4*)src)[i];
        uint4 u = make_uint4(f2tf32(v.x), f2tf32(v.y), f2tf32(v.z), f2tf32(v.w));
        ((uint4*)dst)[i] = u;
    }
}

__global__ __launch_bounds__(256) void transpose_round_kernel(
    const float* __restrict__ src, float* __restrict__ dst, int R, int C)
{
    __shared__ float t[32][33];
    const int x = blockIdx.x * 32 + threadIdx.x;
    const int y0 = blockIdx.y * 32;
#pragma unroll
    for (int i = 0; i < 32; i += 8)
        t[threadIdx.y + i][threadIdx.x] = src[(size_t)(y0 + threadIdx.y + i) * C + x];
    __syncthreads();
    const int nx = blockIdx.y * 32 + threadIdx.x;
    const int ny0 = blockIdx.x * 32;
#pragma unroll
    for (int i = 0; i < 32; i += 8)
        dst[(size_t)(ny0 + threadIdx.y + i) * R + nx] =
            __uint_as_float(f2tf32(t[threadIdx.x][threadIdx.y + i]));
}

// ---------------------------------------------------------------------------
// tf32 GEMM v4: A [M][K], Bt [N][K] (both tf32 bits), C[M][N] fp32.
// CTA tile 256x128, BK=32, 8 warps (wm 0..3 x wn 0..1), warp tile 64x64.
// Per k8-step: 8 LDSM : 32 MMA.
// ---------------------------------------------------------------------------
#define GS_STR 36
#define TG_SMEM ((2*256*GS_STR + 2*128*GS_STR) * (int)sizeof(float))

__global__ __launch_bounds__(256, 1) void tgemm_kernel(
    const float* __restrict__ A, const float* __restrict__ Bt,
    float* __restrict__ C, int M, int N, int K)
{
    extern __shared__ float gsm[];
    float* As = gsm;                         // [2][256][GS_STR]
    float* Bs = gsm + 2 * 256 * GS_STR;      // [2][128][GS_STR]

    const int tid = threadIdx.x;
    const int bx = blockIdx.x, by = blockIdx.y;
    const int lane = tid & 31;
    const int g = lane >> 2, t = lane & 3;
    const int wid = tid >> 5;
    const int m0 = (wid >> 1) * 64;
    const int n0 = (wid & 1) * 64;

    const int a_row = ((lane >> 3) & 1) * 8 + (lane & 7);
    const int a_kw  = (lane >> 4) * 4;
    const int b_row = ((lane >> 4) & 1) * 8 + (lane & 7);
    const int b_kw  = ((lane >> 3) & 1) * 4;

    const int nk = K >> 5;

    auto issue = [&](int st, int k0) {
        float* Ad = As + (size_t)st * 256 * GS_STR;
        float* Bd = Bs + (size_t)st * 128 * GS_STR;
#pragma unroll
        for (int it = 0; it < 8; it++) {
            int idx = tid + it * 256;
            int row = idx >> 3;
            int cw  = (idx & 7) * 4;
            cp16(Ad + row * GS_STR + cw, A + (size_t)(by * 256 + row) * K + k0 + cw);
        }
#pragma unroll
        for (int it = 0; it < 4; it++) {
            int idx = tid + it * 256;
            int row = idx >> 3;
            int cw  = (idx & 7) * 4;
            cp16(Bd + row * GS_STR + cw, Bt + (size_t)(bx * 128 + row) * K + k0 + cw);
        }
        cp_commit();
    };

    issue(0, 0);
    if (nk > 1) issue(1, 32);

    float acc[4][8][4];
#pragma unroll
    for (int mt = 0; mt < 4; mt++)
#pragma unroll
        for (int nt = 0; nt < 8; nt++)
#pragma unroll
            for (int r = 0; r < 4; r++) acc[mt][nt][r] = 0.f;

    for (int i = 0; i < nk; i++) {
        const int st = i & 1;
        float* Ad = As + (size_t)st * 256 * GS_STR;
        float* Bd = Bs + (size_t)st * 128 * GS_STR;
        if (i + 1 < nk) asm volatile("cp.async.wait_group 1;\n");
        else            asm volatile("cp.async.wait_group 0;\n");
        __syncthreads();

#pragma unroll
        for (int kk = 0; kk < 32; kk += 8) {
            unsigned a[4][4], bfr[4][4];
#pragma unroll
            for (int mt = 0; mt < 4; mt++)
                ldsm4(a[mt], Ad + (m0 + mt * 16 + a_row) * GS_STR + kk + a_kw);
#pragma unroll
            for (int p = 0; p < 4; p++)
                ldsm4(bfr[p], Bd + (n0 + p * 16 + b_row) * GS_STR + kk + b_kw);
#pragma unroll
            for (int mt = 0; mt < 4; mt++)
#pragma unroll
                for (int nt = 0; nt < 8; nt++)
                    mma_tf32(acc[mt][nt], a[mt], &bfr[nt >> 1][(nt & 1) * 2]);
        }
        __syncthreads();
        if (i + 2 < nk) issue(st, (i + 2) * 32);
    }

#pragma unroll
    for (int mt = 0; mt < 4; mt++) {
        const int r = by * 256 + m0 + mt * 16 + g;
#pragma unroll
        for (int nt = 0; nt < 8; nt++) {
            const int c = bx * 128 + n0 + nt * 8 + 2 * t;
            *(float2*)(C + (size_t)r * N + c)       = make_float2(acc[mt][nt][0], acc[mt][nt][1]);
            *(float2*)(C + (size_t)(r + 8) * N + c) = make_float2(acc[mt][nt][2], acc[mt][nt][3]);
        }
    }
}

// ---------------------------------------------------------------------------
// Post-process: RMSNorm + RoPE for Q/K, V transpose. tf32 outputs, scale folded.
// ---------------------------------------------------------------------------
__global__ __launch_bounds__(256) void qkv_post_kernel(
    const float* __restrict__ cosp, const float* __restrict__ sinp,
    const float* __restrict__ qw, const float* __restrict__ kw)
{
    const int token = blockIdx.x;
    const int unit  = blockIdx.y;
    const int d     = threadIdx.x;
    const int b = token >> 11;
    const int s = token & 2047;

    __shared__ float sh[DH];
    __shared__ float red[8];

    if (unit < 18) {
        float x;
        const float* w;
        if (unit < 16) {
            x = g_qg[(size_t)token * QGN + unit * 512 + d];
            w = qw;
        } else {
            x = g_kv[(size_t)token * (2*KVN) + (unit - 16) * 256 + d];
            w = kw;
        }
        float v = x * x;
#pragma unroll
        for (int o = 16; o; o >>= 1) v += __shfl_xor_sync(0xffffffffu, v, o);
        if ((d & 31) == 0) red[d >> 5] = v;
        __syncthreads();
        float tot = 0.f;
#pragma unroll
        for (int i = 0; i < 8; i++) tot += red[i];
        float xn = x * rsqrtf(tot * (1.0f / 256.0f) + 1e-6f) * (1.0f + w[d]);
        sh[d] = xn;
        __syncthreads();
        float out = xn;
        if (d < ROT) {
            float rot = (d < 32) ? -sh[d + 32] : sh[d - 32];
            out = xn * cosp[(size_t)token * ROT + d] + rot * sinp[(size_t)token * ROT + d];
        }
        if (unit < 16)
            g_q[(((size_t)b * NH + unit) * SS + s) * DH + d] =
                __uint_as_float(f2tf32(out * 0.0625f));
        else
            g_kr[(((size_t)b * NKVH + (unit - 16)) * SS + s) * DH + d] =
                __uint_as_float(f2tf32(out));
    } else {
        const int kvh = unit - 18;
        g_vr[(((size_t)b * NKVH + kvh) * DH + d) * SS + s] =
            __uint_as_float(f2tf32(g_kv[(size_t)token * (2*KVN) + 512 + kvh * 256 + d]));
    }
}

// ---------------------------------------------------------------------------
// Flash attention v4 (tf32 mma + ldmatrix). q-tile 128 (Q resident in smem),
// key-tile 64, fp32 online softmax, fused sigmoid-gate epilogue.
// 8 warps: wm in {0..3} (32 q-rows each), wn in {0,1} (32 keys / 32 d-cols).
// QK warp tile 32x32 (8 MMA : 4 LDSM per k8); PV same shape.
// ---------------------------------------------------------------------------
#define QS_STR 260
#define KS_STR 68
#define VS_STR 68
#define PS_STR 68
#define FL_SMEM ((128*QS_STR + 64*KS_STR + 64*VS_STR + 128*PS_STR + 512) * 4)

__global__ __launch_bounds__(256, 1) void flash_kernel()
{
    extern __shared__ float sm[];
    float* Qs   = sm;                      // [128][QS_STR] tf32 bits
    float* Ks   = Qs + 128 * QS_STR;       // [key][d] (64-d chunk)
    float* Vs   = Ks + 64 * KS_STR;        // [d][key] (64-d chunk, transposed)
    float* Ps   = Vs + 64 * VS_STR;        // [128][key] tf32 bits
    float* redm = Ps + 128 * PS_STR;       // [wn][128]
    float* redl = redm + 256;              // [wn][128]

    const int tid = threadIdx.x;
    const int lane = tid & 31;
    const int g = lane >> 2, t = lane & 3;
    const int wid = tid >> 5;
    const int wm = wid >> 1;               // 0..3
    const int wn = wid & 1;                // 0..1

    const int a_row = ((lane >> 3) & 1) * 8 + (lane & 7);
    const int a_kw  = (lane >> 4) * 4;
    const int b_row = ((lane >> 4) & 1) * 8 + (lane & 7);
    const int b_kw  = ((lane >> 3) & 1) * 4;

    const int qt = blockIdx.x;
    const int b  = blockIdx.y >> 4;
    const int h  = blockIdx.y & 15;
    const int kvh = h >> 3;
    const int q0 = qt * 128;

    const float* Qp  = g_q  + (((size_t)b * NH + h) * SS + q0) * DH;
    const float* Kp  = g_kr + ((size_t)b * NKVH + kvh) * SS * DH;
    const float* VpT = g_vr + ((size_t)b * NKVH + kvh) * DH * SS;

    // Load Q block (resident): 128 rows x 256
#pragma unroll
    for (int it = 0; it < 32; it++) {
        const int r = it * 4 + (tid >> 6);
        const int c = (tid & 63) * 4;
        *(float4*)&Qs[r * QS_STR + c] = *(const float4*)(Qp + (size_t)r * DH + c);
    }

    float o[2][16][4];     // [mt][chunk*4+nt][frag]
    float mrun[4], lrun[4];
#pragma unroll
    for (int mt = 0; mt < 2; mt++)
#pragma unroll
        for (int cc = 0; cc < 16; cc++)
#pragma unroll
            for (int r = 0; r < 4; r++) o[mt][cc][r] = 0.f;
#pragma unroll
    for (int i = 0; i < 4; i++) { mrun[i] = -1e30f; lrun[i] = 0.f; }

    const int ktmax = 2 * qt + 1;
    for (int kt = 0; kt <= ktmax; kt++) {
        const float* Kt = Kp + (size_t)(kt * 64) * DH;

        float s[2][4][4];
#pragma unroll
        for (int mt = 0; mt < 2; mt++)
#pragma unroll
            for (int nt = 0; nt < 4; nt++)
#pragma unroll
                for (int r = 0; r < 4; r++) s[mt][nt][r] = 0.f;

        // ---- S = Q K^T over D in 4 chunks of 64 ----
        for (int c = 0; c < 4; c++) {
            __syncthreads();
#pragma unroll
            for (int it = 0; it < 4; it++) {
                const int key = it * 16 + (tid >> 4);
                const int col = (tid & 15) * 4;
                *(float4*)&Ks[key * KS_STR + col] =
                    *(const float4*)(Kt + (size_t)key * DH + c * 64 + col);
            }
            __syncthreads();
#pragma unroll
            for (int kk = 0; kk < 64; kk += 8) {
                unsigned a[2][4], bq[2][4];
                ldsm4(a[0], Qs + (wm * 32 + a_row)      * QS_STR + c * 64 + kk + a_kw);
                ldsm4(a[1], Qs + (wm * 32 + 16 + a_row) * QS_STR + c * 64 + kk + a_kw);
                ldsm4(bq[0], Ks + (wn * 32 + b_row)      * KS_STR + kk + b_kw);
                ldsm4(bq[1], Ks + (wn * 32 + 16 + b_row) * KS_STR + kk + b_kw);
#pragma unroll
                for (int mt = 0; mt < 2; mt++)
#pragma unroll
                    for (int nt = 0; nt < 4; nt++)
                        mma_tf32(s[mt][nt], a[mt], &bq[nt >> 1][(nt & 1) * 2]);
            }
        }

        // ---- causal mask (only the two diagonal-straddling tiles) ----
        if (kt >= 2 * qt) {
#pragma unroll
            for (int mt = 0; mt < 2; mt++)
#pragma unroll
                for (int nt = 0; nt < 4; nt++)
#pragma unroll
                    for (int r = 0; r < 4; r++) {
                        const int row = q0 + wm * 32 + mt * 16 + (r >> 1) * 8 + g;
                        const int col = kt * 64 + wn * 32 + nt * 8 + 2 * t + (r & 1);
                        if (col > row) s[mt][nt][r] = -1e30f;
                    }
        }

        // ---- online softmax (rows reduced over t lanes, then 2 wn warps) ----
        float al[4];
#pragma unroll
        for (int mt = 0; mt < 2; mt++)
#pragma unroll
            for (int hh = 0; hh < 2; hh++) {
                float v = -1e30f;
#pragma unroll
                for (int nt = 0; nt < 4; nt++)
                    v = fmaxf(v, fmaxf(s[mt][nt][hh * 2], s[mt][nt][hh * 2 + 1]));
                v = fmaxf(v, __shfl_xor_sync(0xffffffffu, v, 1));
                v = fmaxf(v, __shfl_xor_sync(0xffffffffu, v, 2));
                if (t == 0) redm[wn * 128 + wm * 32 + mt * 16 + hh * 8 + g] = v;
            }
        __syncthreads();
#pragma unroll
        for (int mt = 0; mt < 2; mt++)
#pragma unroll
            for (int hh = 0; hh < 2; hh++) {
                const int idx = mt * 2 + hh;
                const int rl = wm * 32 + mt * 16 + hh * 8 + g;
                float tm = fmaxf(redm[rl], redm[128 + rl]);
                float mn = fmaxf(mrun[idx], tm);
                al[idx] = __expf(mrun[idx] - mn);
                mrun[idx] = mn;
                float rs = 0.f;
#pragma unroll
                for (int nt = 0; nt < 4; nt++)
#pragma unroll
                    for (int j = 0; j < 2; j++) {
                        float p = __expf(s[mt][nt][hh * 2 + j] - mn);
                        s[mt][nt][hh * 2 + j] = p;
                        rs += p;
                    }
                rs += __shfl_xor_sync(0xffffffffu, rs, 1);
                rs += __shfl_xor_sync(0xffffffffu, rs, 2);
                if (t == 0) redl[wn * 128 + rl] = rs;
            }
        // write P (tf32 bits)
#pragma unroll
        for (int mt = 0; mt < 2; mt++)
#pragma unroll
            for (int nt = 0; nt < 4; nt++) {
                const int r = wm * 32 + mt * 16 + g;
                const int c = wn * 32 + nt * 8 + 2 * t;
                Ps[r * PS_STR + c]           = __uint_as_float(f2tf32(s[mt][nt][0]));
                Ps[r * PS_STR + c + 1]       = __uint_as_float(f2tf32(s[mt][nt][1]));
                Ps[(r + 8) * PS_STR + c]     = __uint_as_float(f2tf32(s[mt][nt][2]));
                Ps[(r + 8) * PS_STR + c + 1] = __uint_as_float(f2tf32(s[mt][nt][3]));
            }
        __syncthreads();
#pragma unroll
        for (int mt = 0; mt < 2; mt++)
#pragma unroll
            for (int hh = 0; hh < 2; hh++) {
                const int idx = mt * 2 + hh;
                const int rl = wm * 32 + mt * 16 + hh * 8 + g;
                float ts = redl[rl] + redl[128 + rl];
                lrun[idx] = lrun[idx] * al[idx] + ts;
#pragma unroll
                for (int cc = 0; cc < 16; cc++) {
                    o[mt][cc][hh * 2]     *= al[idx];
                    o[mt][cc][hh * 2 + 1] *= al[idx];
                }
            }

        // ---- O += P V over d in 4 chunks of 64 (Vs = [d][key]) ----
        for (int c = 0; c < 4; c++) {
            if (c) __syncthreads();
#pragma unroll
            for (int it = 0; it < 4; it++) {
                const int dl = it * 16 + (tid >> 4);
                const int key = (tid & 15) * 4;
                *(float4*)&Vs[dl * VS_STR + key] =
                    *(const float4*)(VpT + (size_t)(c * 64 + dl) * SS + kt * 64 + key);
            }
            __syncthreads();
#pragma unroll
            for (int kk = 0; kk < 64; kk += 8) {
                unsigned a[2][4], bv[2][4];
                ldsm4(a[0], Ps + (wm * 32 + a_row)      * PS_STR + kk + a_kw);
                ldsm4(a[1], Ps + (wm * 32 + 16 + a_row) * PS_STR + kk + a_kw);
                ldsm4(bv[0], Vs + (wn * 32 + b_row)      * VS_STR + kk + b_kw);
                ldsm4(bv[1], Vs + (wn * 32 + 16 + b_row) * VS_STR + kk + b_kw);
#pragma unroll
                for (int mt = 0; mt < 2; mt++)
#pragma unroll
                    for (int nt = 0; nt < 4; nt++)
                        mma_tf32(o[mt][c * 4 + nt], a[mt], &bv[nt >> 1][(nt & 1) * 2]);
            }
        }
    }

    // ---- epilogue: /l, * sigmoid(gate), tf32-round for O-projection ----
#pragma unroll
    for (int mt = 0; mt < 2; mt++)
#pragma unroll
        for (int hh = 0; hh < 2; hh++) {
            const int idx = mt * 2 + hh;
            const int row = q0 + wm * 32 + mt * 16 + hh * 8 + g;
            const size_t token = (size_t)b * SS + row;
            const float inv = 1.f / lrun[idx];
#pragma unroll
            for (int cc = 0; cc < 16; cc++) {
                const int col = (cc >> 2) * 64 + wn * 32 + (cc & 3) * 8 + 2 * t;
                float2 gt = *(const float2*)(g_qg + token * QGN + h * 512 + 256 + col);
                unsigned ox = f2tf32(o[mt][cc][hh * 2]     * inv / (1.f + __expf(-gt.x)));
                unsigned oy = f2tf32(o[mt][cc][hh * 2 + 1] * inv / (1.f + __expf(-gt.y)));
                *(uint2*)(g_attn + token * ODIM + h * 256 + col) = make_uint2(ox, oy);
            }
        }
}

// ---------------------------------------------------------------------------
extern "C" void kernel_launch(void* const* d_in, const int* in_sizes, int n_in,
                              void* d_out, int out_size)
{
    (void)in_sizes; (void)n_in; (void)out_size;
    const float* hs   = (const float*)d_in[0];
    const float* cosp = (const float*)d_in[1];
    const float* sinp = (const float*)d_in[2];
    const float* Wq   = (const float*)d_in[3];
    const float* Wk   = (const float*)d_in[4];
    const float* Wv   = (const float*)d_in[5];
    const float* Wo   = (const float*)d_in[6];
    const float* qw   = (const float*)d_in[7];
    const float* kw   = (const float*)d_in[8];
    float* out = (float*)d_out;

    float *p_hs, *p_wqt, *p_wkvt, *p_wot, *p_qg, *p_kv, *p_attn;
    cudaGetSymbolAddress((void**)&p_hs,   g_hs);
    cudaGetSymbolAddress((void**)&p_wqt,  g_wqt);
    cudaGetSymbolAddress((void**)&p_wkvt, g_wkvt);
    cudaGetSymbolAddress((void**)&p_wot,  g_wot);
    cudaGetSymbolAddress((void**)&p_qg,   g_qg);
    cudaGetSymbolAddress((void**)&p_kv,   g_kv);
    cudaGetSymbolAddress((void**)&p_attn, g_attn);

    // 0) Prep: round hs; transpose+round weights
    round_kernel<<<2048, 256>>>(hs, p_hs, MM * HID / 4);
    transpose_round_kernel<<<dim3(QGN / 32, HID / 32), dim3(32, 8)>>>(Wq, p_wqt, HID, QGN);
    transpose_round_kernel<<<dim3(KVN / 32, HID / 32), dim3(32, 8)>>>(Wk, p_wkvt, HID, KVN);
    transpose_round_kernel<<<dim3(KVN / 32, HID / 32), dim3(32, 8)>>>(Wv, p_wkvt + (size_t)KVN * HID, HID, KVN);
    transpose_round_kernel<<<dim3(HID / 32, ODIM / 32), dim3(32, 8)>>>(Wo, p_wot, ODIM, HID);

    // 1) Projections (tf32 mma, ldmatrix, cp.async, 256x128 tiles)
    cudaFuncSetAttribute(tgemm_kernel, cudaFuncAttributeMaxDynamicSharedMemorySize, TG_SMEM);
    tgemm_kernel<<<dim3(QGN / 128, MM / 256), 256, TG_SMEM>>>(p_hs, p_wqt, p_qg, MM, QGN, HID);
    tgemm_kernel<<<dim3(2*KVN / 128, MM / 256), 256, TG_SMEM>>>(p_hs, p_wkvt, p_kv, MM, 2*KVN, HID);

    // 2) RMSNorm + RoPE + V transpose
    qkv_post_kernel<<<dim3(MM, 20), 256>>>(cosp, sinp, qw, kw);

    // 3) Flash attention + gate (q-tile 128)
    cudaFuncSetAttribute(flash_kernel, cudaFuncAttributeMaxDynamicSharedMemorySize, FL_SMEM);
    flash_kernel<<<dim3(SS / 128, BB * NH), 256, FL_SMEM>>>();

    // 4) Output projection
    tgemm_kernel<<<dim3(HID / 128, MM / 256), 256, TG_SMEM>>>(p_attn, p_wot, out, MM, HID, ODIM);
}

// round 6
// speedup vs baseline: 5.6316x; 1.6794x over previous
#include <cuda_runtime.h>
#include <cuda_fp16.h>
#include <math.h>

// Problem constants
#define BB 2
#define SS 2048
#define HID 2048
#define NH 16
#define NKVH 2
#define DH 256
#define ROT 64
#define MM (BB*SS)          // 4096 tokens
#define QGN (NH*DH*2)       // 8192
#define KVN (NKVH*DH)       // 512
#define ODIM (NH*DH)        // 4096

// Scratch (device globals)
__device__ __half g_hs  [(size_t)MM * HID];          // fp16 hidden states
__device__ __half g_wqt [(size_t)QGN * HID];         // Wq^T  [N][K] fp16
__device__ __half g_wkvt[(size_t)(2*KVN) * HID];     // [Wk^T; Wv^T] fp16
__device__ __half g_wot [(size_t)HID * ODIM];        // Wo^T fp16
__device__ float  g_qg  [(size_t)MM * QGN];          // [token][h*512 + (q|gate)] fp32
__device__ float  g_kv  [(size_t)MM * 2*KVN];        // [token][k | v] fp32
__device__ __half g_q   [(size_t)BB * NH  * SS * DH];   // [b][h][s][d], scale folded
__device__ __half g_kr  [(size_t)BB * NKVH * SS * DH];  // [b][kvh][s][d]
__device__ __half g_vr  [(size_t)BB * NKVH * DH * SS];  // [b][kvh][d][s] (TRANSPOSED)
__device__ __half g_attn[(size_t)MM * ODIM];            // fp16 attn output

__device__ __forceinline__ void mma_f16(float c[4], const unsigned a[4], const unsigned* b) {
    asm volatile(
        "mma.sync.aligned.m16n8k16.row.col.f32.f16.f16.f32 "
        "{%0,%1,%2,%3}, {%4,%5,%6,%7}, {%8,%9}, {%0,%1,%2,%3};\n"
        : "+f"(c[0]), "+f"(c[1]), "+f"(c[2]), "+f"(c[3])
        : "r"(a[0]), "r"(a[1]), "r"(a[2]), "r"(a[3]), "r"(b[0]), "r"(b[1]));
}

__device__ __forceinline__ void ldsm4(unsigned r[4], const __half* p) {
    unsigned a = (unsigned)__cvta_generic_to_shared(p);
    asm volatile("ldmatrix.sync.aligned.m8n8.x4.shared.b16 {%0,%1,%2,%3}, [%4];\n"
                 : "=r"(r[0]), "=r"(r[1]), "=r"(r[2]), "=r"(r[3]) : "r"(a));
}

__device__ __forceinline__ void cp16(void* dst, const void* src) {
    unsigned d = (unsigned)__cvta_generic_to_shared(dst);
    asm volatile("cp.async.cg.shared.global [%0], [%1], 16;\n" :: "r"(d), "l"(src));
}
__device__ __forceinline__ void cp_commit() { asm volatile("cp.async.commit_group;\n"); }

// ---------------------------------------------------------------------------
// Prep: fp32 -> fp16, 8 elems/thread
// ---------------------------------------------------------------------------
__global__ __launch_bounds__(256) void half_kernel(const float* __restrict__ src,
                                                   __half* __restrict__ dst, int n8)
{
    for (int i = blockIdx.x * 256 + threadIdx.x; i < n8; i += gridDim.x * 256) {
        float4 v0 = ((const float4*)src)[i * 2];
        float4 v1 = ((const float4*)src)[i * 2 + 1];
        __half2 h[4];
        h[0] = __floats2half2_rn(v0.x, v0.y);
        h[1] = __floats2half2_rn(v0.z, v0.w);
        h[2] = __floats2half2_rn(v1.x, v1.y);
        h[3] = __floats2half2_rn(v1.z, v1.w);
        ((uint4*)dst)[i] = *(uint4*)h;
    }
}

// ---------------------------------------------------------------------------
// Prep: transpose + fp16. src [R][C] fp32 -> dst [C][R] fp16. R,C mult of 32.
// ---------------------------------------------------------------------------
__global__ __launch_bounds__(256) void transpose_half_kernel(
    const float* __restrict__ src, __half* __restrict__ dst, int R, int C)
{
    __shared__ float t[32][33];
    const int x = blockIdx.x * 32 + threadIdx.x;
    const int y0 = blockIdx.y * 32;
#pragma unroll
    for (int i = 0; i < 32; i += 8)
        t[threadIdx.y + i][threadIdx.x] = src[(size_t)(y0 + threadIdx.y + i) * C + x];
    __syncthreads();
    const int nx = blockIdx.y * 32 + threadIdx.x;
    const int ny0 = blockIdx.x * 32;
#pragma unroll
    for (int i = 0; i < 32; i += 8)
        dst[(size_t)(ny0 + threadIdx.y + i) * R + nx] =
            __float2half(t[threadIdx.x][threadIdx.y + i]);
}

// ---------------------------------------------------------------------------
// fp16 GEMM: A [M][K] fp16, Bt [N][K] fp16, C [M][N] fp32.
// CTA tile 256x128, BK=32, double-buffered cp.async, 8 warps (4x2), warp 64x64.
// Per k16-step: 8 LDSM : 32 MMA (k16).
// ---------------------------------------------------------------------------
#define GS_STR 40   // halfs; 80B row stride -> conflict-free ldmatrix
#define TG_SMEM ((2*256*GS_STR + 2*128*GS_STR) * (int)sizeof(__half))

__global__ __launch_bounds__(256, 1) void hgemm_kernel(
    const __half* __restrict__ A, const __half* __restrict__ Bt,
    float* __restrict__ C, int M, int N, int K)
{
    extern __shared__ __half hsm[];
    __half* As = hsm;                        // [2][256][GS_STR]
    __half* Bs = hsm + 2 * 256 * GS_STR;     // [2][128][GS_STR]

    const int tid = threadIdx.x;
    const int bx = blockIdx.x, by = blockIdx.y;
    const int lane = tid & 31;
    const int g = lane >> 2, t = lane & 3;
    const int wid = tid >> 5;
    const int m0 = (wid >> 1) * 64;
    const int n0 = (wid & 1) * 64;

    const int a_row = ((lane >> 3) & 1) * 8 + (lane & 7);
    const int a_kh  = (lane >> 4) * 8;       // halfs
    const int b_row = ((lane >> 4) & 1) * 8 + (lane & 7);
    const int b_kh  = ((lane >> 3) & 1) * 8; // halfs

    const int nk = K >> 5;

    auto issue = [&](int st, int k0) {
        __half* Ad = As + (size_t)st * 256 * GS_STR;
        __half* Bd = Bs + (size_t)st * 128 * GS_STR;
#pragma unroll
        for (int it = 0; it < 4; it++) {
            int idx = tid + it * 256;        // 0..1023
            int row = idx >> 2;              // 0..255
            int ch  = (idx & 3) * 8;         // half offset
            cp16(Ad + row * GS_STR + ch, A + (size_t)(by * 256 + row) * K + k0 + ch);
        }
#pragma unroll
        for (int it = 0; it < 2; it++) {
            int idx = tid + it * 256;        // 0..511
            int row = idx >> 2;              // 0..127
            int ch  = (idx & 3) * 8;
            cp16(Bd + row * GS_STR + ch, Bt + (size_t)(bx * 128 + row) * K + k0 + ch);
        }
        cp_commit();
    };

    issue(0, 0);
    if (nk > 1) issue(1, 32);

    float acc[4][8][4];
#pragma unroll
    for (int mt = 0; mt < 4; mt++)
#pragma unroll
        for (int nt = 0; nt < 8; nt++)
#pragma unroll
            for (int r = 0; r < 4; r++) acc[mt][nt][r] = 0.f;

    for (int i = 0; i < nk; i++) {
        const int st = i & 1;
        __half* Ad = As + (size_t)st * 256 * GS_STR;
        __half* Bd = Bs + (size_t)st * 128 * GS_STR;
        if (i + 1 < nk) asm volatile("cp.async.wait_group 1;\n");
        else            asm volatile("cp.async.wait_group 0;\n");
        __syncthreads();

#pragma unroll
        for (int kk = 0; kk < 32; kk += 16) {
            unsigned a[4][4], bfr[4][4];
#pragma unroll
            for (int mt = 0; mt < 4; mt++)
                ldsm4(a[mt], Ad + (m0 + mt * 16 + a_row) * GS_STR + kk + a_kh);
#pragma unroll
            for (int p = 0; p < 4; p++)
                ldsm4(bfr[p], Bd + (n0 + p * 16 + b_row) * GS_STR + kk + b_kh);
#pragma unroll
            for (int mt = 0; mt < 4; mt++)
#pragma unroll
                for (int nt = 0; nt < 8; nt++)
                    mma_f16(acc[mt][nt], a[mt], &bfr[nt >> 1][(nt & 1) * 2]);
        }
        __syncthreads();
        if (i + 2 < nk) issue(st, (i + 2) * 32);
    }

#pragma unroll
    for (int mt = 0; mt < 4; mt++) {
        const int r = by * 256 + m0 + mt * 16 + g;
#pragma unroll
        for (int nt = 0; nt < 8; nt++) {
            const int c = bx * 128 + n0 + nt * 8 + 2 * t;
            *(float2*)(C + (size_t)r * N + c)       = make_float2(acc[mt][nt][0], acc[mt][nt][1]);
            *(float2*)(C + (size_t)(r + 8) * N + c) = make_float2(acc[mt][nt][2], acc[mt][nt][3]);
        }
    }
}

// ---------------------------------------------------------------------------
// Post-process: RMSNorm + RoPE for Q/K, V transpose. fp16 outputs, scale folded.
// ---------------------------------------------------------------------------
__global__ __launch_bounds__(256) void qkv_post_kernel(
    const float* __restrict__ cosp, const float* __restrict__ sinp,
    const float* __restrict__ qw, const float* __restrict__ kw)
{
    const int token = blockIdx.x;
    const int unit  = blockIdx.y;
    const int d     = threadIdx.x;
    const int b = token >> 11;
    const int s = token & 2047;

    __shared__ float sh[DH];
    __shared__ float red[8];

    if (unit < 18) {
        float x;
        const float* w;
        if (unit < 16) {
            x = g_qg[(size_t)token * QGN + unit * 512 + d];
            w = qw;
        } else {
            x = g_kv[(size_t)token * (2*KVN) + (unit - 16) * 256 + d];
            w = kw;
        }
        float v = x * x;
#pragma unroll
        for (int o = 16; o; o >>= 1) v += __shfl_xor_sync(0xffffffffu, v, o);
        if ((d & 31) == 0) red[d >> 5] = v;
        __syncthreads();
        float tot = 0.f;
#pragma unroll
        for (int i = 0; i < 8; i++) tot += red[i];
        float xn = x * rsqrtf(tot * (1.0f / 256.0f) + 1e-6f) * (1.0f + w[d]);
        sh[d] = xn;
        __syncthreads();
        float out = xn;
        if (d < ROT) {
            float rot = (d < 32) ? -sh[d + 32] : sh[d - 32];
            out = xn * cosp[(size_t)token * ROT + d] + rot * sinp[(size_t)token * ROT + d];
        }
        if (unit < 16)
            g_q[(((size_t)b * NH + unit) * SS + s) * DH + d] = __float2half(out * 0.0625f);
        else
            g_kr[(((size_t)b * NKVH + (unit - 16)) * SS + s) * DH + d] = __float2half(out);
    } else {
        const int kvh = unit - 18;
        g_vr[(((size_t)b * NKVH + kvh) * DH + d) * SS + s] =
            __float2half(g_kv[(size_t)token * (2*KVN) + 512 + kvh * 256 + d]);
    }
}

// ---------------------------------------------------------------------------
// Flash attention v5 (fp16 mma m16n8k16 + ldmatrix). q-tile 128 (Q resident),
// key-tile 64, full-D K tile resident, fp32 online softmax, sigmoid-gate epi.
// 8 warps: wm 0..3 (32 q-rows), wn 0..1 (32 keys in QK / 128 d-cols in PV).
// ---------------------------------------------------------------------------
#define QS_STR 264
#define KS_STR 264
#define VS_STR 72
#define PS_STR 72
#define FL_SMEM ((128*QS_STR + 64*KS_STR + 256*VS_STR + 128*PS_STR) * 2 + 512 * 4)

__global__ __launch_bounds__(256, 1) void flash_kernel()
{
    extern __shared__ __half smh[];
    __half* Qs = smh;                        // [128][QS_STR]
    __half* Ks = Qs + 128 * QS_STR;          // [64][KS_STR]   (full D=256)
    __half* Vs = Ks + 64 * KS_STR;           // [256][VS_STR]  ([d][key])
    __half* Ps = Vs + 256 * VS_STR;          // [128][PS_STR]
    float* redm = (float*)(Ps + 128 * PS_STR);   // [2][128]
    float* redl = redm + 256;                    // [2][128]

    const int tid = threadIdx.x;
    const int lane = tid & 31;
    const int g = lane >> 2, t = lane & 3;
    const int wid = tid >> 5;
    const int wm = wid >> 1;                 // 0..3
    const int wn = wid & 1;                  // 0..1

    const int a_row = ((lane >> 3) & 1) * 8 + (lane & 7);
    const int a_kh  = (lane >> 4) * 8;
    const int b_row = ((lane >> 4) & 1) * 8 + (lane & 7);
    const int b_kh  = ((lane >> 3) & 1) * 8;

    const int qt = blockIdx.x;
    const int b  = blockIdx.y >> 4;
    const int h  = blockIdx.y & 15;
    const int kvh = h >> 3;
    const int q0 = qt * 128;

    const __half* Qp  = g_q  + (((size_t)b * NH + h) * SS + q0) * DH;
    const __half* Kp  = g_kr + ((size_t)b * NKVH + kvh) * SS * DH;
    const __half* VpT = g_vr + ((size_t)b * NKVH + kvh) * DH * SS;

    // Load Q block (resident): 128 rows x 256 halfs
#pragma unroll
    for (int it = 0; it < 16; it++) {
        const int idx = tid + it * 256;      // 0..4095 chunks of 8 halfs
        const int r = idx >> 5;
        const int c = (idx & 31) * 8;
        *(uint4*)&Qs[r * QS_STR + c] = *(const uint4*)(Qp + (size_t)r * DH + c);
    }

    float o[2][16][4];     // [mt][d n8-tile][frag]  (warp d-range = wn*128)
    float mrun[4], lrun[4];
#pragma unroll
    for (int mt = 0; mt < 2; mt++)
#pragma unroll
        for (int cc = 0; cc < 16; cc++)
#pragma unroll
            for (int r = 0; r < 4; r++) o[mt][cc][r] = 0.f;
#pragma unroll
    for (int i = 0; i < 4; i++) { mrun[i] = -1e30f; lrun[i] = 0.f; }

    const int ktmax = 2 * qt + 1;
    for (int kt = 0; kt <= ktmax; kt++) {
        const __half* Kt = Kp + (size_t)(kt * 64) * DH;

        __syncthreads();
        // Load K tile: 64 keys x 256 halfs; V tile: 256 d x 64 keys
#pragma unroll
        for (int it = 0; it < 8; it++) {
            const int idx = tid + it * 256;  // 0..2047 chunks
            const int key = idx >> 5;
            const int col = (idx & 31) * 8;
            *(uint4*)&Ks[key * KS_STR + col] = *(const uint4*)(Kt + (size_t)key * DH + col);
            const int dl = idx >> 3;
            const int kc = (idx & 7) * 8;
            *(uint4*)&Vs[dl * VS_STR + kc] =
                *(const uint4*)(VpT + (size_t)dl * SS + kt * 64 + kc);
        }
        __syncthreads();

        float s[2][4][4];
#pragma unroll
        for (int mt = 0; mt < 2; mt++)
#pragma unroll
            for (int nt = 0; nt < 4; nt++)
#pragma unroll
                for (int r = 0; r < 4; r++) s[mt][nt][r] = 0.f;

        // ---- S = Q K^T over D=256, k16 steps ----
#pragma unroll
        for (int kk = 0; kk < 256; kk += 16) {
            unsigned a[2][4], bq[2][4];
            ldsm4(a[0], Qs + (wm * 32 + a_row)      * QS_STR + kk + a_kh);
            ldsm4(a[1], Qs + (wm * 32 + 16 + a_row) * QS_STR + kk + a_kh);
            ldsm4(bq[0], Ks + (wn * 32 + b_row)      * KS_STR + kk + b_kh);
            ldsm4(bq[1], Ks + (wn * 32 + 16 + b_row) * KS_STR + kk + b_kh);
#pragma unroll
            for (int mt = 0; mt < 2; mt++)
#pragma unroll
                for (int nt = 0; nt < 4; nt++)
                    mma_f16(s[mt][nt], a[mt], &bq[nt >> 1][(nt & 1) * 2]);
        }

        // ---- causal mask (diagonal-straddling tiles only) ----
        if (kt >= 2 * qt) {
#pragma unroll
            for (int mt = 0; mt < 2; mt++)
#pragma unroll
                for (int nt = 0; nt < 4; nt++)
#pragma unroll
                    for (int r = 0; r < 4; r++) {
                        const int row = q0 + wm * 32 + mt * 16 + (r >> 1) * 8 + g;
                        const int col = kt * 64 + wn * 32 + nt * 8 + 2 * t + (r & 1);
                        if (col > row) s[mt][nt][r] = -1e30f;
                    }
        }

        // ---- online softmax ----
        float al[4];
#pragma unroll
        for (int mt = 0; mt < 2; mt++)
#pragma unroll
            for (int hh = 0; hh < 2; hh++) {
                float v = -1e30f;
#pragma unroll
                for (int nt = 0; nt < 4; nt++)
                    v = fmaxf(v, fmaxf(s[mt][nt][hh * 2], s[mt][nt][hh * 2 + 1]));
                v = fmaxf(v, __shfl_xor_sync(0xffffffffu, v, 1));
                v = fmaxf(v, __shfl_xor_sync(0xffffffffu, v, 2));
                if (t == 0) redm[wn * 128 + wm * 32 + mt * 16 + hh * 8 + g] = v;
            }
        __syncthreads();
#pragma unroll
        for (int mt = 0; mt < 2; mt++)
#pragma unroll
            for (int hh = 0; hh < 2; hh++) {
                const int idx = mt * 2 + hh;
                const int rl = wm * 32 + mt * 16 + hh * 8 + g;
                float tm = fmaxf(redm[rl], redm[128 + rl]);
                float mn = fmaxf(mrun[idx], tm);
                al[idx] = __expf(mrun[idx] - mn);
                mrun[idx] = mn;
                float rs = 0.f;
#pragma unroll
                for (int nt = 0; nt < 4; nt++)
#pragma unroll
                    for (int j = 0; j < 2; j++) {
                        float p = __expf(s[mt][nt][hh * 2 + j] - mn);
                        s[mt][nt][hh * 2 + j] = p;
                        rs += p;
                    }
                rs += __shfl_xor_sync(0xffffffffu, rs, 1);
                rs += __shfl_xor_sync(0xffffffffu, rs, 2);
                if (t == 0) redl[wn * 128 + rl] = rs;
            }
        // write P (fp16)
#pragma unroll
        for (int mt = 0; mt < 2; mt++)
#pragma unroll
            for (int nt = 0; nt < 4; nt++) {
                const int r = wm * 32 + mt * 16 + g;
                const int c = wn * 32 + nt * 8 + 2 * t;
                *(__half2*)&Ps[r * PS_STR + c] =
                    __floats2half2_rn(s[mt][nt][0], s[mt][nt][1]);
                *(__half2*)&Ps[(r + 8) * PS_STR + c] =
                    __floats2half2_rn(s[mt][nt][2], s[mt][nt][3]);
            }
        __syncthreads();
#pragma unroll
        for (int mt = 0; mt < 2; mt++)
#pragma unroll
            for (int hh = 0; hh < 2; hh++) {
                const int idx = mt * 2 + hh;
                const int rl = wm * 32 + mt * 16 + hh * 8 + g;
                float ts = redl[rl] + redl[128 + rl];
                lrun[idx] = lrun[idx] * al[idx] + ts;
#pragma unroll
                for (int cc = 0; cc < 16; cc++) {
                    o[mt][cc][hh * 2]     *= al[idx];
                    o[mt][cc][hh * 2 + 1] *= al[idx];
                }
            }

        // ---- O += P V (warp covers d = wn*128..+127; Vs = [d][key]) ----
#pragma unroll
        for (int kk = 0; kk < 64; kk += 16) {
            unsigned a[2][4], bv[8][4];
            ldsm4(a[0], Ps + (wm * 32 + a_row)      * PS_STR + kk + a_kh);
            ldsm4(a[1], Ps + (wm * 32 + 16 + a_row) * PS_STR + kk + a_kh);
#pragma unroll
            for (int p = 0; p < 8; p++)
                ldsm4(bv[p], Vs + (wn * 128 + p * 16 + b_row) * VS_STR + kk + b_kh);
#pragma unroll
            for (int mt = 0; mt < 2; mt++)
#pragma unroll
                for (int nt = 0; nt < 16; nt++)
                    mma_f16(o[mt][nt], a[mt], &bv[nt >> 1][(nt & 1) * 2]);
        }
    }

    // ---- epilogue: /l, * sigmoid(gate), fp16 out for O-projection ----
#pragma unroll
    for (int mt = 0; mt < 2; mt++)
#pragma unroll
        for (int hh = 0; hh < 2; hh++) {
            const int idx = mt * 2 + hh;
            const int row = q0 + wm * 32 + mt * 16 + hh * 8 + g;
            const size_t token = (size_t)b * SS + row;
            const float inv = 1.f / lrun[idx];
#pragma unroll
            for (int cc = 0; cc < 16; cc++) {
                const int col = wn * 128 + cc * 8 + 2 * t;
                float2 gt = *(const float2*)(g_qg + token * QGN + h * 512 + 256 + col);
                float ox = o[mt][cc][hh * 2]     * inv / (1.f + __expf(-gt.x));
                float oy = o[mt][cc][hh * 2 + 1] * inv / (1.f + __expf(-gt.y));
                *(__half2*)(g_attn + token * ODIM + h * 256 + col) =
                    __floats2half2_rn(ox, oy);
            }
        }
}

// ---------------------------------------------------------------------------
extern "C" void kernel_launch(void* const* d_in, const int* in_sizes, int n_in,
                              void* d_out, int out_size)
{
    (void)in_sizes; (void)n_in; (void)out_size;
    const float* hs   = (const float*)d_in[0];
    const float* cosp = (const float*)d_in[1];
    const float* sinp = (const float*)d_in[2];
    const float* Wq   = (const float*)d_in[3];
    const float* Wk   = (const float*)d_in[4];
    const float* Wv   = (const float*)d_in[5];
    const float* Wo   = (const float*)d_in[6];
    const float* qw   = (const float*)d_in[7];
    const float* kw   = (const float*)d_in[8];
    float* out = (float*)d_out;

    __half *p_hs, *p_wqt, *p_wkvt, *p_wot, *p_attn;
    float *p_qg, *p_kv;
    cudaGetSymbolAddress((void**)&p_hs,   g_hs);
    cudaGetSymbolAddress((void**)&p_wqt,  g_wqt);
    cudaGetSymbolAddress((void**)&p_wkvt, g_wkvt);
    cudaGetSymbolAddress((void**)&p_wot,  g_wot);
    cudaGetSymbolAddress((void**)&p_qg,   g_qg);
    cudaGetSymbolAddress((void**)&p_kv,   g_kv);
    cudaGetSymbolAddress((void**)&p_attn, g_attn);

    // 0) Prep: fp16 hs; transpose+fp16 weights
    half_kernel<<<1024, 256>>>(hs, p_hs, MM * HID / 8);
    transpose_half_kernel<<<dim3(QGN / 32, HID / 32), dim3(32, 8)>>>(Wq, p_wqt, HID, QGN);
    transpose_half_kernel<<<dim3(KVN / 32, HID / 32), dim3(32, 8)>>>(Wk, p_wkvt, HID, KVN);
    transpose_half_kernel<<<dim3(KVN / 32, HID / 32), dim3(32, 8)>>>(Wv, p_wkvt + (size_t)KVN * HID, HID, KVN);
    transpose_half_kernel<<<dim3(HID / 32, ODIM / 32), dim3(32, 8)>>>(Wo, p_wot, ODIM, HID);

    // 1) Projections (fp16 mma m16n8k16)
    cudaFuncSetAttribute(hgemm_kernel, cudaFuncAttributeMaxDynamicSharedMemorySize, TG_SMEM);
    hgemm_kernel<<<dim3(QGN / 128, MM / 256), 256, TG_SMEM>>>(p_hs, p_wqt, p_qg, MM, QGN, HID);
    hgemm_kernel<<<dim3(2*KVN / 128, MM / 256), 256, TG_SMEM>>>(p_hs, p_wkvt, p_kv, MM, 2*KVN, HID);

    // 2) RMSNorm + RoPE + V transpose (fp16 outputs)
    qkv_post_kernel<<<dim3(MM, 20), 256>>>(cosp, sinp, qw, kw);

    // 3) Flash attention + gate (fp16 mma, q-tile 128)
    cudaFuncSetAttribute(flash_kernel, cudaFuncAttributeMaxDynamicSharedMemorySize, FL_SMEM);
    flash_kernel<<<dim3(SS / 128, BB * NH), 256, FL_SMEM>>>();

    // 4) Output projection
    hgemm_kernel<<<dim3(HID / 128, MM / 256), 256, TG_SMEM>>>(p_attn, p_wot, out, MM, HID, ODIM);
}